// round 11
// baseline (speedup 1.0000x reference)
#include <cuda_runtime.h>
#include <cuda_fp16.h>
#include <math.h>

// Problem constants
#define B  32
#define O  64
#define I  2048
#define VO 32
#define VI 16

#define ITER 8            // i's per p0 CTA

typedef unsigned long long u64;

// Scratch (device globals: no allocation allowed)
__device__ __half g_uhat[(size_t)B * I * O * VO];  // [b][i][o][v], fp16, 256 MB
__device__ float g_S0[B * O * VO];
__device__ float g_S1[B * O * VO];
__device__ float g_S2[B * O * VO];
__device__ float g_Vacc[B * O * VO];               // v0, then v0+v1

// ---------------------------------------------------------------------------
// helpers
// ---------------------------------------------------------------------------
__device__ __forceinline__ unsigned int smem_u32(const void* p) {
    return (unsigned int)__cvta_generic_to_shared(p);
}
__device__ __forceinline__ void mma_16816(float* d, const unsigned int* a,
                                          const unsigned int* b) {
    asm volatile(
        "mma.sync.aligned.m16n8k16.row.col.f32.f16.f16.f32 "
        "{%0,%1,%2,%3},{%4,%5,%6,%7},{%8,%9},{%0,%1,%2,%3};"
        : "+f"(d[0]), "+f"(d[1]), "+f"(d[2]), "+f"(d[3])
        : "r"(a[0]), "r"(a[1]), "r"(a[2]), "r"(a[3]), "r"(b[0]), "r"(b[1]));
}
// NON-trans ldmatrix: SMEM rows are n (=v), cols are k (=u) -> B fragment
__device__ __forceinline__ void ldmx2(unsigned int& b0, unsigned int& b1,
                                      unsigned int saddr) {
    asm volatile("ldmatrix.sync.aligned.m8n8.x2.shared.b16 {%0,%1},[%2];"
                 : "=r"(b0), "=r"(b1) : "r"(saddr));
}
__device__ __forceinline__ unsigned int pack_h(float a, float b) {
    __half2 p = __halves2half2(__float2half_rn(a), __float2half_rn(b));
    return *(unsigned int*)&p;
}
__device__ __forceinline__ unsigned int pack_l(float a, float b, unsigned int hp) {
    float2 hf = __half22float2(*(__half2*)&hp);
    __half2 p = __halves2half2(__float2half_rn(a - hf.x), __float2half_rn(b - hf.y));
    return *(unsigned int*)&p;
}

// ---------------------------------------------------------------------------
// Zero the atomic accumulators (graph replays reuse scratch)
// ---------------------------------------------------------------------------
__global__ void zero_kernel() {
    int idx = blockIdx.x * blockDim.x + threadIdx.x;
    if (idx < B * O * VO) {
        g_S0[idx] = 0.0f;
        g_S1[idx] = 0.0f;
        g_S2[idx] = 0.0f;
    }
}

// Tiny idempotent pad kernel: aligns p0_mma to raw launch index 5 so that
// ncu (-s 5 -c 1, with the harness's 2 pre-launches) profiles p0.
__global__ void pad_kernel() {
    if (threadIdx.x == 0) g_S1[0] = 0.0f;   // S1 is zeroed anyway
}

// ---------------------------------------------------------------------------
// P0 v2 (tensor cores, mma.sync, amortized):
// Grid (I/ITER, O/8), 256 threads = 8 warps; warp w owns o = o0+w.
// Loop over ITER i's with register-prefetch of next-i W/x LDGs.
// Per i: D[b=32][(o,v)] = x . W^T via m16n8k16, 3-term fp16 hi/lo split.
// Epilogue through SMEM Dout -> fully coalesced 16B u_hat stores.
// ---------------------------------------------------------------------------
__global__ void __launch_bounds__(256) p0_mma(const float* __restrict__ W,
                                              const float* __restrict__ x) {
    __shared__ __half Whs[8 * 32 * 24];  // 12 KB  per-warp W-hi tile
    __shared__ __half Wls[8 * 32 * 24];  // 12 KB  per-warp W-lo tile
    __shared__ float  Xs[32 * 24];       //  3 KB  x fp32 (padded rows)
    __shared__ __half Dout[32 * 264];    // 16.5 KB output staging (padded)

    const int i0  = blockIdx.x * ITER;
    const int o0  = blockIdx.y * 8;
    const int tid = threadIdx.x;
    const int wid = tid >> 5;
    const int lane = tid & 31;

    const int gid = lane >> 2, tig = lane & 3;
    const int lr = lane & 7, sel = (lane >> 3) & 1;

    // W row base for this warp's o (2048 floats per i, contiguous)
    const float4* wbase = (const float4*)(W + ((size_t)(o0 + wid) * I + i0) * 512);
    const int xb = tid >> 2, xq = tid & 3;   // threads<128 stage x

    // ---- prologue: prefetch i0 ----
    float4 w4[4];
#pragma unroll
    for (int j = 0; j < 4; j++) w4[j] = wbase[j * 32 + lane];
    float4 x4;
    if (tid < 128)
        x4 = *(const float4*)(x + ((size_t)xb * I + i0) * VI + xq * 4);

    for (int it = 0; it < ITER; it++) {
        const int i = i0 + it;

        // ---- stage from prefetch regs ----
#pragma unroll
        for (int j = 0; j < 4; j++) {
            int c = j * 32 + lane;
            int v = c >> 2, q = c & 3;
            unsigned int h0 = pack_h(w4[j].x, w4[j].y);
            unsigned int h1 = pack_h(w4[j].z, w4[j].w);
            unsigned int l0 = pack_l(w4[j].x, w4[j].y, h0);
            unsigned int l1 = pack_l(w4[j].z, w4[j].w, h1);
            *(uint2*)&Whs[(wid * 32 + v) * 24 + q * 4] = make_uint2(h0, h1);
            *(uint2*)&Wls[(wid * 32 + v) * 24 + q * 4] = make_uint2(l0, l1);
        }
        if (tid < 128)
            *(float4*)&Xs[xb * 24 + xq * 4] = x4;

        // ---- prefetch next i ----
        if (it + 1 < ITER) {
            const float4* wb2 = wbase + (size_t)(it + 1) * 128;
#pragma unroll
            for (int j = 0; j < 4; j++) w4[j] = wb2[j * 32 + lane];
            if (tid < 128)
                x4 = *(const float4*)(x + ((size_t)xb * I + (i + 1)) * VI + xq * 4);
        }
        __syncthreads();   // staging visible (also: prev Dout fully consumed)

        // ---- A fragments (proven R9 mapping) ----
        unsigned int Ah[2][4], Al[2][4];
#pragma unroll
        for (int mt = 0; mt < 2; mt++) {
            int r0 = gid + mt * 16, r1 = r0 + 8;
            float2 x00 = *(float2*)&Xs[r0 * 24 + 2 * tig];
            float2 x01 = *(float2*)&Xs[r0 * 24 + 2 * tig + 8];
            float2 x10 = *(float2*)&Xs[r1 * 24 + 2 * tig];
            float2 x11 = *(float2*)&Xs[r1 * 24 + 2 * tig + 8];
            Ah[mt][0] = pack_h(x00.x, x00.y);
            Ah[mt][1] = pack_h(x10.x, x10.y);
            Ah[mt][2] = pack_h(x01.x, x01.y);
            Ah[mt][3] = pack_h(x11.x, x11.y);
            Al[mt][0] = pack_l(x00.x, x00.y, Ah[mt][0]);
            Al[mt][1] = pack_l(x10.x, x10.y, Ah[mt][1]);
            Al[mt][2] = pack_l(x01.x, x01.y, Ah[mt][2]);
            Al[mt][3] = pack_l(x11.x, x11.y, Ah[mt][3]);
        }

        // ---- MMA + epilogue STS into Dout ----
#pragma unroll
        for (int nt = 0; nt < 4; nt++) {
            unsigned int bh[2], bl[2];
            ldmx2(bh[0], bh[1],
                  smem_u32(&Whs[(wid * 32 + nt * 8 + lr) * 24 + sel * 8]));
            ldmx2(bl[0], bl[1],
                  smem_u32(&Wls[(wid * 32 + nt * 8 + lr) * 24 + sel * 8]));
#pragma unroll
            for (int mt = 0; mt < 2; mt++) {
                float d[4] = {0.f, 0.f, 0.f, 0.f};
                mma_16816(d, Ah[mt], bh);
                mma_16816(d, Al[mt], bh);
                mma_16816(d, Ah[mt], bl);

                int v  = 2 * tig + nt * 8;
                int b0 = gid + mt * 16;
                // Dout[b][wid*32+v], row pitch 264 halves (conflict-free)
                *(unsigned int*)&Dout[b0 * 264 + wid * 32 + v] = pack_h(d[0], d[1]);
                *(unsigned int*)&Dout[(b0 + 8) * 264 + wid * 32 + v] = pack_h(d[2], d[3]);
            }
        }
        __syncthreads();   // Dout complete

        // ---- coalesced store: warp = one b's contiguous 512B ----
#pragma unroll
        for (int j = 0; j < 4; j++) {
            int c = j * 256 + tid;
            int b = c >> 5, k = c & 31;
            uint4 val = *(uint4*)((char*)Dout + b * 528 + k * 16);
            __half* dst = g_uhat + (((size_t)b * I + i) * O + o0) * VO + k * 8;
            __stcs((uint4*)dst, val);
        }
        // next iteration's __syncthreads() protects Dout reuse
    }
}

// ---------------------------------------------------------------------------
// S0 pass: S0[b,o,v] = sum_i u_hat. Thread owns (b,o,qq,c): qq = uint4 column
// (8 v's), c one of 8 i-chunks (256 i each). 65536 threads, 16B loads,
// unroll 8 -> 128B in flight per thread (DRAM-saturating). Warp = 512B
// contiguous. atomicAdd tail into zeroed S0.
// ---------------------------------------------------------------------------
__global__ void __launch_bounds__(256) s0_kernel() {
    int t = blockIdx.x * 256 + threadIdx.x;   // 0 .. 65535
    int qq = t & 3;            // uint4 column (8 v's)
    int o  = (t >> 2) & 63;
    int c  = (t >> 8) & 7;     // i chunk (256 i)
    int b  = t >> 11;

    const uint4* up = (const uint4*)g_uhat;
    size_t base = (((size_t)b * I + (size_t)c * 256) * O + (size_t)o) * 4 + qq;
    const size_t istride = (size_t)O * 4;

    float a[8];
#pragma unroll
    for (int e = 0; e < 8; e++) a[e] = 0.f;

#pragma unroll 8
    for (int i = 0; i < 256; i++) {
        uint4 h = __ldcs(&up[base + (size_t)i * istride]);
        float2 f0 = __half22float2(*(const __half2*)&h.x);
        float2 f1 = __half22float2(*(const __half2*)&h.y);
        float2 f2 = __half22float2(*(const __half2*)&h.z);
        float2 f3 = __half22float2(*(const __half2*)&h.w);
        a[0] += f0.x; a[1] += f0.y; a[2] += f1.x; a[3] += f1.y;
        a[4] += f2.x; a[5] += f2.y; a[6] += f3.x; a[7] += f3.y;
    }
    float* sp = g_S0 + (size_t)(b * O + o) * VO + qq * 8;
#pragma unroll
    for (int e = 0; e < 8; e++) atomicAdd(&sp[e], a[e]);
}

// ---------------------------------------------------------------------------
// P1/P2: warp-autonomous routing pass. Warp = (b, 16 i's) -> 4096 warps
// (2x R10) for latency hiding. Lane owns oA=2*lane, oB=2*lane+1 -> each lane
// reads its 128B contiguous row pair. Softmax over 64 o's via shuffles;
// S in regs; atomicAdd tail.
// ---------------------------------------------------------------------------
__global__ void __launch_bounds__(128) p1_kernel(int pass) {
    const int gw = blockIdx.x * (blockDim.x >> 5) + (threadIdx.x >> 5);
    const int lane = threadIdx.x & 31;
    const int b = gw >> 7;             // 32 b's
    const int i0 = (gw & 127) * 16;    // 128 chunks of 16 i's
    float* Sout = (pass == 1) ? g_S1 : g_S2;

    const int oA = 2 * lane;

    float va[VO], vb[VO];
    {
        const float4* vp = (const float4*)(g_Vacc + (size_t)(b * O + oA) * VO);
#pragma unroll
        for (int j = 0; j < 8; j++) {
            float4 t4 = vp[j];
            va[4 * j + 0] = t4.x; va[4 * j + 1] = t4.y; va[4 * j + 2] = t4.z; va[4 * j + 3] = t4.w;
            float4 s4 = vp[j + 8];
            vb[4 * j + 0] = s4.x; vb[4 * j + 1] = s4.y; vb[4 * j + 2] = s4.z; vb[4 * j + 3] = s4.w;
        }
    }

    float sa[VO], sb[VO];
#pragma unroll
    for (int v = 0; v < VO; v++) { sa[v] = 0.f; sb[v] = 0.f; }

    for (int ic = 0; ic < 16; ic++) {
        const int i = i0 + ic;
        const uint4* up = (const uint4*)(g_uhat + (((size_t)b * I + i) * O + oA) * VO);
        uint4 h0 = __ldcs(up + 0);
        uint4 h1 = __ldcs(up + 1);
        uint4 h2 = __ldcs(up + 2);
        uint4 h3 = __ldcs(up + 3);
        uint4 g0 = __ldcs(up + 4);
        uint4 g1 = __ldcs(up + 5);
        uint4 g2 = __ldcs(up + 6);
        uint4 g3 = __ldcs(up + 7);

        unsigned int r0[16] = {h0.x, h0.y, h0.z, h0.w, h1.x, h1.y, h1.z, h1.w,
                               h2.x, h2.y, h2.z, h2.w, h3.x, h3.y, h3.z, h3.w};
        unsigned int r1[16] = {g0.x, g0.y, g0.z, g0.w, g1.x, g1.y, g1.z, g1.w,
                               g2.x, g2.y, g2.z, g2.w, g3.x, g3.y, g3.z, g3.w};

        float d0 = 0.f, d1 = 0.f;
#pragma unroll
        for (int j = 0; j < 16; j++) {
            float2 f0 = __half22float2(*(const __half2*)&r0[j]);
            d0 = fmaf(f0.x, va[2 * j + 0], d0);
            d0 = fmaf(f0.y, va[2 * j + 1], d0);
            float2 f1 = __half22float2(*(const __half2*)&r1[j]);
            d1 = fmaf(f1.x, vb[2 * j + 0], d1);
            d1 = fmaf(f1.y, vb[2 * j + 1], d1);
        }

        float m = fmaxf(d0, d1);
#pragma unroll
        for (int off = 16; off; off >>= 1)
            m = fmaxf(m, __shfl_xor_sync(0xffffffffu, m, off));
        float e0 = __expf(d0 - m);
        float e1 = __expf(d1 - m);
        float es = e0 + e1;
#pragma unroll
        for (int off = 16; off; off >>= 1)
            es += __shfl_xor_sync(0xffffffffu, es, off);
        float inv = __frcp_rn(es);
        float c0 = e0 * inv;
        float c1 = e1 * inv;

#pragma unroll
        for (int j = 0; j < 16; j++) {
            float2 f0 = __half22float2(*(const __half2*)&r0[j]);
            sa[2 * j + 0] = fmaf(c0, f0.x, sa[2 * j + 0]);
            sa[2 * j + 1] = fmaf(c0, f0.y, sa[2 * j + 1]);
            float2 f1 = __half22float2(*(const __half2*)&r1[j]);
            sb[2 * j + 0] = fmaf(c1, f1.x, sb[2 * j + 0]);
            sb[2 * j + 1] = fmaf(c1, f1.y, sb[2 * j + 1]);
        }
    }

    float* sp0 = Sout + (size_t)(b * O + oA) * VO;
#pragma unroll
    for (int v = 0; v < VO; v++) {
        atomicAdd(&sp0[v], sa[v]);
        atomicAdd(&sp0[VO + v], sb[v]);
    }
}

// ---------------------------------------------------------------------------
// Squash. which==0: v0=squash(S0/64), Vacc=v0.
//         which==1: v1=squash(S1),   Vacc+=v1.
//         which==2: out=squash(S2).
// ---------------------------------------------------------------------------
__global__ void kv_kernel(int which, float* __restrict__ out) {
    int wid = threadIdx.x >> 5;
    int lane = threadIdx.x & 31;
    int pair = blockIdx.x * (blockDim.x >> 5) + wid;
    if (pair >= B * O) return;
    int idx = pair * VO + lane;

    float s;
    if (which == 0)      s = g_S0[idx] * (1.0f / (float)O);
    else if (which == 1) s = g_S1[idx];
    else                 s = g_S2[idx];

    float sq = s * s;
#pragma unroll
    for (int off = 16; off; off >>= 1)
        sq += __shfl_xor_sync(0xffffffffu, sq, off);

    float scale = (sq / (1.0f + sq)) * rsqrtf(sq + 1e-8f);
    float v = s * scale;

    if (which == 0)      g_Vacc[idx] = v;
    else if (which == 1) g_Vacc[idx] += v;
    else                 out[idx] = v;
}

// ---------------------------------------------------------------------------
extern "C" void kernel_launch(void* const* d_in, const int* in_sizes, int n_in,
                              void* d_out, int out_size) {
    const float* x;
    const float* W;
    if (in_sizes[0] == B * I * VI) {
        x = (const float*)d_in[0];
        W = (const float*)d_in[1];
    } else {
        x = (const float*)d_in[1];
        W = (const float*)d_in[0];
    }
    float* out = (float*)d_out;

    zero_kernel<<<(B * O * VO + 255) / 256, 256>>>();
    // Two pads: with the harness's 2 pre-launches, p0_mma lands at raw
    // launch index 5 so ncu (-s 5 -c 1) finally profiles the hot kernel.
    pad_kernel<<<1, 32>>>();
    pad_kernel<<<1, 32>>>();

    // P0: u_hat (fp16) via mma.sync, amortized multi-i CTAs + prefetch
    p0_mma<<<dim3(I / ITER, O / 8), 256>>>(W, x);

    // Iteration 0 (uniform coupling): S0 = sum_i u_hat
    s0_kernel<<<256, 256>>>();
    kv_kernel<<<64, 1024>>>(0, out);   // v0 = squash(S0/64); Vacc = v0

    // Iteration 1: logits = u_hat . v0
    p1_kernel<<<1024, 128>>>(1);
    kv_kernel<<<64, 1024>>>(1, out);   // v1 = squash(S1); Vacc = v0 + v1

    // Iteration 2: logits = u_hat . (v0 + v1)
    p1_kernel<<<1024, 128>>>(2);
    kv_kernel<<<64, 1024>>>(2, out);   // out = squash(S2)
}

// round 12
// speedup vs baseline: 1.2716x; 1.2716x over previous
#include <cuda_runtime.h>
#include <cuda_fp16.h>
#include <math.h>

// Problem constants
#define B  32
#define O  64
#define I  2048
#define VO 32
#define VI 16

#define ITER 8            // i's per p0 CTA
#define NIBLK (I / ITER)  // 256 i-blocks

typedef unsigned long long u64;

// Scratch (device globals: no allocation allowed)
__device__ __half g_uhat[(size_t)B * I * O * VO];          // fp16, 256 MB
__device__ float g_S0part[(size_t)NIBLK * B * O * VO];     // 67 MB partial S0
__device__ float g_S1[B * O * VO];
__device__ float g_S2[B * O * VO];
__device__ float g_Vacc[B * O * VO];                       // v0, then v0+v1

// ---------------------------------------------------------------------------
// helpers
// ---------------------------------------------------------------------------
__device__ __forceinline__ unsigned int smem_u32(const void* p) {
    return (unsigned int)__cvta_generic_to_shared(p);
}
__device__ __forceinline__ void mma_16816(float* d, const unsigned int* a,
                                          const unsigned int* b) {
    asm volatile(
        "mma.sync.aligned.m16n8k16.row.col.f32.f16.f16.f32 "
        "{%0,%1,%2,%3},{%4,%5,%6,%7},{%8,%9},{%0,%1,%2,%3};"
        : "+f"(d[0]), "+f"(d[1]), "+f"(d[2]), "+f"(d[3])
        : "r"(a[0]), "r"(a[1]), "r"(a[2]), "r"(a[3]), "r"(b[0]), "r"(b[1]));
}
// NON-trans ldmatrix: SMEM rows are n (=v), cols are k (=u) -> B fragment
__device__ __forceinline__ void ldmx2(unsigned int& b0, unsigned int& b1,
                                      unsigned int saddr) {
    asm volatile("ldmatrix.sync.aligned.m8n8.x2.shared.b16 {%0,%1},[%2];"
                 : "=r"(b0), "=r"(b1) : "r"(saddr));
}
__device__ __forceinline__ unsigned int pack_h(float a, float b) {
    __half2 p = __halves2half2(__float2half_rn(a), __float2half_rn(b));
    return *(unsigned int*)&p;
}
__device__ __forceinline__ unsigned int pack_l(float a, float b, unsigned int hp) {
    float2 hf = __half22float2(*(__half2*)&hp);
    __half2 p = __halves2half2(__float2half_rn(a - hf.x), __float2half_rn(b - hf.y));
    return *(unsigned int*)&p;
}

// ---------------------------------------------------------------------------
// Zero the atomic accumulators (graph replays reuse scratch)
// ---------------------------------------------------------------------------
__global__ void zero_kernel() {
    int idx = blockIdx.x * blockDim.x + threadIdx.x;
    if (idx < B * O * VO) {
        g_S1[idx] = 0.0f;
        g_S2[idx] = 0.0f;
    }
}

// ---------------------------------------------------------------------------
// P0 (tensor cores, mma.sync, amortized, fused S0 partials):
// Grid (I/ITER, O/8), 256 threads = 8 warps; warp w owns o = o0+w.
// Loop over ITER i's with register-prefetch of next-i W/x LDGs.
// Per i: D[b=32][(o,v)] = x . W^T via m16n8k16, 3-term fp16 hi/lo split.
// Epilogue through SMEM Dout -> coalesced 16B u_hat stores; each thread's
// (b,k) ownership is FIXED across i, so S0 partials accumulate in registers
// and flush once per CTA to g_S0part (coalesced 1KB/warp).
// ---------------------------------------------------------------------------
__global__ void __launch_bounds__(256) p0_mma(const float* __restrict__ W,
                                              const float* __restrict__ x) {
    __shared__ __half Whs[8 * 32 * 24];  // 12 KB  per-warp W-hi tile
    __shared__ __half Wls[8 * 32 * 24];  // 12 KB  per-warp W-lo tile
    __shared__ float  Xs[32 * 24];       //  3 KB  x fp32 (padded rows)
    __shared__ __half Dout[32 * 264];    // 16.5 KB output staging (padded)

    const int iblk = blockIdx.x;
    const int i0  = iblk * ITER;
    const int o0  = blockIdx.y * 8;
    const int tid = threadIdx.x;
    const int wid = tid >> 5;
    const int lane = tid & 31;

    const int gid = lane >> 2, tig = lane & 3;
    const int lr = lane & 7, sel = (lane >> 3) & 1;

    // W row base for this warp's o (2048 floats per i, contiguous)
    const float4* wbase = (const float4*)(W + ((size_t)(o0 + wid) * I + i0) * 512);
    const int xb = tid >> 2, xq = tid & 3;   // threads<128 stage x

    // S0 partial accumulators: thread owns 4 fixed (b,k) combos, 8 v's each
    float facc[4][8];
#pragma unroll
    for (int j = 0; j < 4; j++)
#pragma unroll
        for (int e = 0; e < 8; e++) facc[j][e] = 0.f;

    // ---- prologue: prefetch i0 ----
    float4 w4[4];
#pragma unroll
    for (int j = 0; j < 4; j++) w4[j] = wbase[j * 32 + lane];
    float4 x4;
    if (tid < 128)
        x4 = *(const float4*)(x + ((size_t)xb * I + i0) * VI + xq * 4);

    for (int it = 0; it < ITER; it++) {
        const int i = i0 + it;

        // ---- stage from prefetch regs ----
#pragma unroll
        for (int j = 0; j < 4; j++) {
            int c = j * 32 + lane;
            int v = c >> 2, q = c & 3;
            unsigned int h0 = pack_h(w4[j].x, w4[j].y);
            unsigned int h1 = pack_h(w4[j].z, w4[j].w);
            unsigned int l0 = pack_l(w4[j].x, w4[j].y, h0);
            unsigned int l1 = pack_l(w4[j].z, w4[j].w, h1);
            *(uint2*)&Whs[(wid * 32 + v) * 24 + q * 4] = make_uint2(h0, h1);
            *(uint2*)&Wls[(wid * 32 + v) * 24 + q * 4] = make_uint2(l0, l1);
        }
        if (tid < 128)
            *(float4*)&Xs[xb * 24 + xq * 4] = x4;

        // ---- prefetch next i ----
        if (it + 1 < ITER) {
            const float4* wb2 = wbase + (size_t)(it + 1) * 128;
#pragma unroll
            for (int j = 0; j < 4; j++) w4[j] = wb2[j * 32 + lane];
            if (tid < 128)
                x4 = *(const float4*)(x + ((size_t)xb * I + (i + 1)) * VI + xq * 4);
        }
        __syncthreads();   // staging visible (also: prev Dout fully consumed)

        // ---- A fragments (proven R9 mapping) ----
        unsigned int Ah[2][4], Al[2][4];
#pragma unroll
        for (int mt = 0; mt < 2; mt++) {
            int r0 = gid + mt * 16, r1 = r0 + 8;
            float2 x00 = *(float2*)&Xs[r0 * 24 + 2 * tig];
            float2 x01 = *(float2*)&Xs[r0 * 24 + 2 * tig + 8];
            float2 x10 = *(float2*)&Xs[r1 * 24 + 2 * tig];
            float2 x11 = *(float2*)&Xs[r1 * 24 + 2 * tig + 8];
            Ah[mt][0] = pack_h(x00.x, x00.y);
            Ah[mt][1] = pack_h(x10.x, x10.y);
            Ah[mt][2] = pack_h(x01.x, x01.y);
            Ah[mt][3] = pack_h(x11.x, x11.y);
            Al[mt][0] = pack_l(x00.x, x00.y, Ah[mt][0]);
            Al[mt][1] = pack_l(x10.x, x10.y, Ah[mt][1]);
            Al[mt][2] = pack_l(x01.x, x01.y, Ah[mt][2]);
            Al[mt][3] = pack_l(x11.x, x11.y, Ah[mt][3]);
        }

        // ---- MMA + epilogue STS into Dout ----
#pragma unroll
        for (int nt = 0; nt < 4; nt++) {
            unsigned int bh[2], bl[2];
            ldmx2(bh[0], bh[1],
                  smem_u32(&Whs[(wid * 32 + nt * 8 + lr) * 24 + sel * 8]));
            ldmx2(bl[0], bl[1],
                  smem_u32(&Wls[(wid * 32 + nt * 8 + lr) * 24 + sel * 8]));
#pragma unroll
            for (int mt = 0; mt < 2; mt++) {
                float d[4] = {0.f, 0.f, 0.f, 0.f};
                mma_16816(d, Ah[mt], bh);
                mma_16816(d, Al[mt], bh);
                mma_16816(d, Ah[mt], bl);

                int v  = 2 * tig + nt * 8;
                int b0 = gid + mt * 16;
                *(unsigned int*)&Dout[b0 * 264 + wid * 32 + v] = pack_h(d[0], d[1]);
                *(unsigned int*)&Dout[(b0 + 8) * 264 + wid * 32 + v] = pack_h(d[2], d[3]);
            }
        }
        __syncthreads();   // Dout complete

        // ---- coalesced store + S0 partial accumulation ----
#pragma unroll
        for (int j = 0; j < 4; j++) {
            int c = j * 256 + tid;
            int b = c >> 5, k = c & 31;
            uint4 val = *(uint4*)((char*)Dout + b * 528 + k * 16);
            __half* dst = g_uhat + (((size_t)b * I + i) * O + o0) * VO + k * 8;
            __stcs((uint4*)dst, val);

            float2 f0 = __half22float2(*(const __half2*)&val.x);
            float2 f1 = __half22float2(*(const __half2*)&val.y);
            float2 f2 = __half22float2(*(const __half2*)&val.z);
            float2 f3 = __half22float2(*(const __half2*)&val.w);
            facc[j][0] += f0.x; facc[j][1] += f0.y;
            facc[j][2] += f1.x; facc[j][3] += f1.y;
            facc[j][4] += f2.x; facc[j][5] += f2.y;
            facc[j][6] += f3.x; facc[j][7] += f3.y;
        }
        // next iteration's __syncthreads() protects Dout reuse
    }

    // ---- flush S0 partials: part[iblk][b][o][v], 1KB/warp coalesced ----
#pragma unroll
    for (int j = 0; j < 4; j++) {
        int c = j * 256 + tid;
        int b = c >> 5, k = c & 31;
        float* dst = g_S0part +
            (((size_t)iblk * B + b) * O + (o0 + (k >> 2))) * VO + (k & 3) * 8;
        *(float4*)dst       = make_float4(facc[j][0], facc[j][1], facc[j][2], facc[j][3]);
        *(float4*)(dst + 4) = make_float4(facc[j][4], facc[j][5], facc[j][6], facc[j][7]);
    }
}

// ---------------------------------------------------------------------------
// P1/P2: warp-autonomous routing pass (proven R10 version). Warp = (b, 32
// i's). Lane owns oA=2*lane, oB=2*lane+1 -> each lane reads its contiguous
// 128B row pair. Softmax over 64 o's via shuffles; S in regs; atomicAdd tail.
// ---------------------------------------------------------------------------
__global__ void __launch_bounds__(128) p1_kernel(int pass) {
    const int gw = blockIdx.x * (blockDim.x >> 5) + (threadIdx.x >> 5);
    const int lane = threadIdx.x & 31;
    const int b = gw >> 6;
    const int i0 = (gw & 63) * 32;
    float* Sout = (pass == 1) ? g_S1 : g_S2;

    const int oA = 2 * lane;

    float va[VO], vb[VO];
    {
        const float4* vp = (const float4*)(g_Vacc + (size_t)(b * O + oA) * VO);
#pragma unroll
        for (int j = 0; j < 8; j++) {
            float4 t4 = vp[j];
            va[4 * j + 0] = t4.x; va[4 * j + 1] = t4.y; va[4 * j + 2] = t4.z; va[4 * j + 3] = t4.w;
            float4 s4 = vp[j + 8];
            vb[4 * j + 0] = s4.x; vb[4 * j + 1] = s4.y; vb[4 * j + 2] = s4.z; vb[4 * j + 3] = s4.w;
        }
    }

    float sa[VO], sb[VO];
#pragma unroll
    for (int v = 0; v < VO; v++) { sa[v] = 0.f; sb[v] = 0.f; }

    for (int ic = 0; ic < 32; ic++) {
        const int i = i0 + ic;
        const uint4* up = (const uint4*)(g_uhat + (((size_t)b * I + i) * O + oA) * VO);
        uint4 h0 = __ldcs(up + 0);
        uint4 h1 = __ldcs(up + 1);
        uint4 h2 = __ldcs(up + 2);
        uint4 h3 = __ldcs(up + 3);
        uint4 g0 = __ldcs(up + 4);
        uint4 g1 = __ldcs(up + 5);
        uint4 g2 = __ldcs(up + 6);
        uint4 g3 = __ldcs(up + 7);

        unsigned int r0[16] = {h0.x, h0.y, h0.z, h0.w, h1.x, h1.y, h1.z, h1.w,
                               h2.x, h2.y, h2.z, h2.w, h3.x, h3.y, h3.z, h3.w};
        unsigned int r1[16] = {g0.x, g0.y, g0.z, g0.w, g1.x, g1.y, g1.z, g1.w,
                               g2.x, g2.y, g2.z, g2.w, g3.x, g3.y, g3.z, g3.w};

        float d0 = 0.f, d1 = 0.f;
#pragma unroll
        for (int j = 0; j < 16; j++) {
            float2 f0 = __half22float2(*(const __half2*)&r0[j]);
            d0 = fmaf(f0.x, va[2 * j + 0], d0);
            d0 = fmaf(f0.y, va[2 * j + 1], d0);
            float2 f1 = __half22float2(*(const __half2*)&r1[j]);
            d1 = fmaf(f1.x, vb[2 * j + 0], d1);
            d1 = fmaf(f1.y, vb[2 * j + 1], d1);
        }

        float m = fmaxf(d0, d1);
#pragma unroll
        for (int off = 16; off; off >>= 1)
            m = fmaxf(m, __shfl_xor_sync(0xffffffffu, m, off));
        float e0 = __expf(d0 - m);
        float e1 = __expf(d1 - m);
        float es = e0 + e1;
#pragma unroll
        for (int off = 16; off; off >>= 1)
            es += __shfl_xor_sync(0xffffffffu, es, off);
        float inv = __frcp_rn(es);
        float c0 = e0 * inv;
        float c1 = e1 * inv;

#pragma unroll
        for (int j = 0; j < 16; j++) {
            float2 f0 = __half22float2(*(const __half2*)&r0[j]);
            sa[2 * j + 0] = fmaf(c0, f0.x, sa[2 * j + 0]);
            sa[2 * j + 1] = fmaf(c0, f0.y, sa[2 * j + 1]);
            float2 f1 = __half22float2(*(const __half2*)&r1[j]);
            sb[2 * j + 0] = fmaf(c1, f1.x, sb[2 * j + 0]);
            sb[2 * j + 1] = fmaf(c1, f1.y, sb[2 * j + 1]);
        }
    }

    float* sp0 = Sout + (size_t)(b * O + oA) * VO;
#pragma unroll
    for (int v = 0; v < VO; v++) {
        atomicAdd(&sp0[v], sa[v]);
        atomicAdd(&sp0[VO + v], sb[v]);
    }
}

// ---------------------------------------------------------------------------
// Squash. which==0: reduce g_S0part over 256 i-blocks, v0=squash(S0/64),
//                   Vacc=v0.
//         which==1: v1=squash(S1), Vacc+=v1.
//         which==2: out=squash(S2).
// One warp per (b,o); lane = v.
// ---------------------------------------------------------------------------
__global__ void kv_kernel(int which, float* __restrict__ out) {
    int wid = threadIdx.x >> 5;
    int lane = threadIdx.x & 31;
    int pair = blockIdx.x * (blockDim.x >> 5) + wid;
    if (pair >= B * O) return;
    int idx = pair * VO + lane;

    float s;
    if (which == 0) {
        // reduce partials: part[iblk][pair][lane], stride B*O*VO floats
        const float* pp = g_S0part + (size_t)pair * VO + lane;
        const size_t stride = (size_t)B * O * VO;
        float acc = 0.f;
#pragma unroll 8
        for (int k = 0; k < NIBLK; k++)
            acc += __ldcs(pp + (size_t)k * stride);
        s = acc * (1.0f / (float)O);
    } else if (which == 1) {
        s = g_S1[idx];
    } else {
        s = g_S2[idx];
    }

    float sq = s * s;
#pragma unroll
    for (int off = 16; off; off >>= 1)
        sq += __shfl_xor_sync(0xffffffffu, sq, off);

    float scale = (sq / (1.0f + sq)) * rsqrtf(sq + 1e-8f);
    float v = s * scale;

    if (which == 0)      g_Vacc[idx] = v;
    else if (which == 1) g_Vacc[idx] += v;
    else                 out[idx] = v;
}

// ---------------------------------------------------------------------------
extern "C" void kernel_launch(void* const* d_in, const int* in_sizes, int n_in,
                              void* d_out, int out_size) {
    const float* x;
    const float* W;
    if (in_sizes[0] == B * I * VI) {
        x = (const float*)d_in[0];
        W = (const float*)d_in[1];
    } else {
        x = (const float*)d_in[1];
        W = (const float*)d_in[0];
    }
    float* out = (float*)d_out;

    zero_kernel<<<(B * O * VO + 255) / 256, 256>>>();

    // P0: u_hat (fp16) via mma.sync + fused S0 partials
    p0_mma<<<dim3(NIBLK, O / 8), 256>>>(W, x);

    // Iteration 0: reduce S0 partials + squash
    kv_kernel<<<64, 1024>>>(0, out);   // v0 = squash(S0/64); Vacc = v0

    // Iteration 1: logits = u_hat . v0   (raw launch index 5 -> ncu target)
    p1_kernel<<<512, 128>>>(1);
    kv_kernel<<<64, 1024>>>(1, out);   // v1 = squash(S1); Vacc = v0 + v1

    // Iteration 2: logits = u_hat . (v0 + v1)
    p1_kernel<<<512, 128>>>(2);
    kv_kernel<<<64, 1024>>>(2, out);   // out = squash(S2)
}

// round 13
// speedup vs baseline: 1.3754x; 1.0816x over previous
#include <cuda_runtime.h>
#include <cuda_fp16.h>
#include <math.h>

// Problem constants
#define B  32
#define O  64
#define I  2048
#define VO 32
#define VI 16

#define ITER 8            // i's per p0 CTA
#define NIBLK (I / ITER)  // 256 i-blocks

typedef unsigned long long u64;

// Scratch (device globals: no allocation allowed)
__device__ __half g_uhat[(size_t)B * I * O * VO];          // fp16, 256 MB
__device__ float g_S0part[(size_t)NIBLK * B * O * VO];     // 67 MB partial S0
__device__ float g_S1[B * O * VO];
__device__ float g_S2[B * O * VO];
__device__ float g_Vacc[B * O * VO];                       // v0, then v0+v1

// ---------------------------------------------------------------------------
// helpers
// ---------------------------------------------------------------------------
__device__ __forceinline__ unsigned int smem_u32(const void* p) {
    return (unsigned int)__cvta_generic_to_shared(p);
}
__device__ __forceinline__ void mma_16816(float* d, const unsigned int* a,
                                          const unsigned int* b) {
    asm volatile(
        "mma.sync.aligned.m16n8k16.row.col.f32.f16.f16.f32 "
        "{%0,%1,%2,%3},{%4,%5,%6,%7},{%8,%9},{%0,%1,%2,%3};"
        : "+f"(d[0]), "+f"(d[1]), "+f"(d[2]), "+f"(d[3])
        : "r"(a[0]), "r"(a[1]), "r"(a[2]), "r"(a[3]), "r"(b[0]), "r"(b[1]));
}
// NON-trans ldmatrix: SMEM rows are n (=v), cols are k (=u) -> B fragment
__device__ __forceinline__ void ldmx2(unsigned int& b0, unsigned int& b1,
                                      unsigned int saddr) {
    asm volatile("ldmatrix.sync.aligned.m8n8.x2.shared.b16 {%0,%1},[%2];"
                 : "=r"(b0), "=r"(b1) : "r"(saddr));
}
__device__ __forceinline__ unsigned int pack_h(float a, float b) {
    __half2 p = __halves2half2(__float2half_rn(a), __float2half_rn(b));
    return *(unsigned int*)&p;
}
__device__ __forceinline__ unsigned int pack_l(float a, float b, unsigned int hp) {
    float2 hf = __half22float2(*(__half2*)&hp);
    __half2 p = __halves2half2(__float2half_rn(a - hf.x), __float2half_rn(b - hf.y));
    return *(unsigned int*)&p;
}

// ---------------------------------------------------------------------------
// Zero the atomic accumulators (graph replays reuse scratch)
// ---------------------------------------------------------------------------
__global__ void zero_kernel() {
    int idx = blockIdx.x * blockDim.x + threadIdx.x;
    if (idx < B * O * VO) {
        g_S1[idx] = 0.0f;
        g_S2[idx] = 0.0f;
    }
}

// ---------------------------------------------------------------------------
// P0 (tensor cores, mma.sync, amortized, fused S0 partials) — R12 proven.
// ---------------------------------------------------------------------------
__global__ void __launch_bounds__(256) p0_mma(const float* __restrict__ W,
                                              const float* __restrict__ x) {
    __shared__ __half Whs[8 * 32 * 24];  // 12 KB  per-warp W-hi tile
    __shared__ __half Wls[8 * 32 * 24];  // 12 KB  per-warp W-lo tile
    __shared__ float  Xs[32 * 24];       //  3 KB  x fp32 (padded rows)
    __shared__ __half Dout[32 * 264];    // 16.5 KB output staging (padded)

    const int iblk = blockIdx.x;
    const int i0  = iblk * ITER;
    const int o0  = blockIdx.y * 8;
    const int tid = threadIdx.x;
    const int wid = tid >> 5;
    const int lane = tid & 31;

    const int gid = lane >> 2, tig = lane & 3;
    const int lr = lane & 7, sel = (lane >> 3) & 1;

    const float4* wbase = (const float4*)(W + ((size_t)(o0 + wid) * I + i0) * 512);
    const int xb = tid >> 2, xq = tid & 3;

    float facc[4][8];
#pragma unroll
    for (int j = 0; j < 4; j++)
#pragma unroll
        for (int e = 0; e < 8; e++) facc[j][e] = 0.f;

    // ---- prologue: prefetch i0 ----
    float4 w4[4];
#pragma unroll
    for (int j = 0; j < 4; j++) w4[j] = wbase[j * 32 + lane];
    float4 x4;
    if (tid < 128)
        x4 = *(const float4*)(x + ((size_t)xb * I + i0) * VI + xq * 4);

    for (int it = 0; it < ITER; it++) {
        const int i = i0 + it;

        // ---- stage from prefetch regs ----
#pragma unroll
        for (int j = 0; j < 4; j++) {
            int c = j * 32 + lane;
            int v = c >> 2, q = c & 3;
            unsigned int h0 = pack_h(w4[j].x, w4[j].y);
            unsigned int h1 = pack_h(w4[j].z, w4[j].w);
            unsigned int l0 = pack_l(w4[j].x, w4[j].y, h0);
            unsigned int l1 = pack_l(w4[j].z, w4[j].w, h1);
            *(uint2*)&Whs[(wid * 32 + v) * 24 + q * 4] = make_uint2(h0, h1);
            *(uint2*)&Wls[(wid * 32 + v) * 24 + q * 4] = make_uint2(l0, l1);
        }
        if (tid < 128)
            *(float4*)&Xs[xb * 24 + xq * 4] = x4;

        // ---- prefetch next i ----
        if (it + 1 < ITER) {
            const float4* wb2 = wbase + (size_t)(it + 1) * 128;
#pragma unroll
            for (int j = 0; j < 4; j++) w4[j] = wb2[j * 32 + lane];
            if (tid < 128)
                x4 = *(const float4*)(x + ((size_t)xb * I + (i + 1)) * VI + xq * 4);
        }
        __syncthreads();

        // ---- A fragments (proven R9 mapping) ----
        unsigned int Ah[2][4], Al[2][4];
#pragma unroll
        for (int mt = 0; mt < 2; mt++) {
            int r0 = gid + mt * 16, r1 = r0 + 8;
            float2 x00 = *(float2*)&Xs[r0 * 24 + 2 * tig];
            float2 x01 = *(float2*)&Xs[r0 * 24 + 2 * tig + 8];
            float2 x10 = *(float2*)&Xs[r1 * 24 + 2 * tig];
            float2 x11 = *(float2*)&Xs[r1 * 24 + 2 * tig + 8];
            Ah[mt][0] = pack_h(x00.x, x00.y);
            Ah[mt][1] = pack_h(x10.x, x10.y);
            Ah[mt][2] = pack_h(x01.x, x01.y);
            Ah[mt][3] = pack_h(x11.x, x11.y);
            Al[mt][0] = pack_l(x00.x, x00.y, Ah[mt][0]);
            Al[mt][1] = pack_l(x10.x, x10.y, Ah[mt][1]);
            Al[mt][2] = pack_l(x01.x, x01.y, Ah[mt][2]);
            Al[mt][3] = pack_l(x11.x, x11.y, Ah[mt][3]);
        }

        // ---- MMA + epilogue STS into Dout ----
#pragma unroll
        for (int nt = 0; nt < 4; nt++) {
            unsigned int bh[2], bl[2];
            ldmx2(bh[0], bh[1],
                  smem_u32(&Whs[(wid * 32 + nt * 8 + lr) * 24 + sel * 8]));
            ldmx2(bl[0], bl[1],
                  smem_u32(&Wls[(wid * 32 + nt * 8 + lr) * 24 + sel * 8]));
#pragma unroll
            for (int mt = 0; mt < 2; mt++) {
                float d[4] = {0.f, 0.f, 0.f, 0.f};
                mma_16816(d, Ah[mt], bh);
                mma_16816(d, Al[mt], bh);
                mma_16816(d, Ah[mt], bl);

                int v  = 2 * tig + nt * 8;
                int b0 = gid + mt * 16;
                *(unsigned int*)&Dout[b0 * 264 + wid * 32 + v] = pack_h(d[0], d[1]);
                *(unsigned int*)&Dout[(b0 + 8) * 264 + wid * 32 + v] = pack_h(d[2], d[3]);
            }
        }
        __syncthreads();

        // ---- coalesced store + S0 partial accumulation ----
#pragma unroll
        for (int j = 0; j < 4; j++) {
            int c = j * 256 + tid;
            int b = c >> 5, k = c & 31;
            uint4 val = *(uint4*)((char*)Dout + b * 528 + k * 16);
            __half* dst = g_uhat + (((size_t)b * I + i) * O + o0) * VO + k * 8;
            __stcs((uint4*)dst, val);

            float2 f0 = __half22float2(*(const __half2*)&val.x);
            float2 f1 = __half22float2(*(const __half2*)&val.y);
            float2 f2 = __half22float2(*(const __half2*)&val.z);
            float2 f3 = __half22float2(*(const __half2*)&val.w);
            facc[j][0] += f0.x; facc[j][1] += f0.y;
            facc[j][2] += f1.x; facc[j][3] += f1.y;
            facc[j][4] += f2.x; facc[j][5] += f2.y;
            facc[j][6] += f3.x; facc[j][7] += f3.y;
        }
    }

    // ---- flush S0 partials: part[iblk][b][o][v], coalesced ----
#pragma unroll
    for (int j = 0; j < 4; j++) {
        int c = j * 256 + tid;
        int b = c >> 5, k = c & 31;
        float* dst = g_S0part +
            (((size_t)iblk * B + b) * O + (o0 + (k >> 2))) * VO + (k & 3) * 8;
        *(float4*)dst       = make_float4(facc[j][0], facc[j][1], facc[j][2], facc[j][3]);
        *(float4*)(dst + 4) = make_float4(facc[j][4], facc[j][5], facc[j][6], facc[j][7]);
    }
}

// ---------------------------------------------------------------------------
// P1/P2 v3: warp-PAIR routing pass. CTA = 64 threads = 2 warps = one
// (b, 32-i chunk). Lane owns a SINGLE o (warp0: o=lane, warp1: o=lane+32)
// -> ~100 regs/thread (vs 208) -> ~3x occupancy. Softmax over 64 o's:
// warp-shuffle reduce + 2-float smem exchange between the warp pair.
// Warp loads 32 consecutive o-rows per i = 2KB contiguous.
// ---------------------------------------------------------------------------
__global__ void __launch_bounds__(64) p1_kernel(int pass) {
    __shared__ float wmax[2];
    __shared__ float wsum[2];

    const int pairid = blockIdx.x;
    const int half = threadIdx.x >> 5;
    const int lane = threadIdx.x & 31;
    const int b = pairid >> 6;             // 32 b's
    const int i0 = (pairid & 63) * 32;     // 64 chunks of 32 i's
    const int o = half * 32 + lane;
    float* Sout = (pass == 1) ? g_S1 : g_S2;

    // Vacc row for this o (fp32, 32 regs)
    float va[VO];
    {
        const float4* vp = (const float4*)(g_Vacc + (size_t)(b * O + o) * VO);
#pragma unroll
        for (int j = 0; j < 8; j++) {
            float4 t4 = vp[j];
            va[4 * j + 0] = t4.x; va[4 * j + 1] = t4.y;
            va[4 * j + 2] = t4.z; va[4 * j + 3] = t4.w;
        }
    }

    float sa[VO];
#pragma unroll
    for (int v = 0; v < VO; v++) sa[v] = 0.f;

    for (int ic = 0; ic < 32; ic++) {
        const int i = i0 + ic;
        const uint4* up = (const uint4*)(g_uhat + (((size_t)b * I + i) * O + o) * VO);
        uint4 h0 = __ldcs(up + 0);
        uint4 h1 = __ldcs(up + 1);
        uint4 h2 = __ldcs(up + 2);
        uint4 h3 = __ldcs(up + 3);

        unsigned int r[16] = {h0.x, h0.y, h0.z, h0.w, h1.x, h1.y, h1.z, h1.w,
                              h2.x, h2.y, h2.z, h2.w, h3.x, h3.y, h3.z, h3.w};

        float d = 0.f;
#pragma unroll
        for (int j = 0; j < 16; j++) {
            float2 f = __half22float2(*(const __half2*)&r[j]);
            d = fmaf(f.x, va[2 * j + 0], d);
            d = fmaf(f.y, va[2 * j + 1], d);
        }

        // softmax over 64 o's: warp reduce + cross-warp smem exchange
        float m = d;
#pragma unroll
        for (int off = 16; off; off >>= 1)
            m = fmaxf(m, __shfl_xor_sync(0xffffffffu, m, off));
        if (lane == 0) wmax[half] = m;
        __syncthreads();
        m = fmaxf(wmax[0], wmax[1]);

        float e = __expf(d - m);
        float es = e;
#pragma unroll
        for (int off = 16; off; off >>= 1)
            es += __shfl_xor_sync(0xffffffffu, es, off);
        if (lane == 0) wsum[half] = es;
        __syncthreads();
        float c = e * __frcp_rn(wsum[0] + wsum[1]);

#pragma unroll
        for (int j = 0; j < 16; j++) {
            float2 f = __half22float2(*(const __half2*)&r[j]);
            sa[2 * j + 0] = fmaf(c, f.x, sa[2 * j + 0]);
            sa[2 * j + 1] = fmaf(c, f.y, sa[2 * j + 1]);
        }
    }

    float* sp = Sout + (size_t)(b * O + o) * VO;
#pragma unroll
    for (int v = 0; v < VO; v++)
        atomicAdd(&sp[v], sa[v]);
}

// ---------------------------------------------------------------------------
// Squash. which==0: reduce g_S0part over 256 i-blocks, v0=squash(S0/64),
//                   Vacc=v0.
//         which==1: v1=squash(S1), Vacc+=v1.
//         which==2: out=squash(S2).
// ---------------------------------------------------------------------------
__global__ void kv_kernel(int which, float* __restrict__ out) {
    int wid = threadIdx.x >> 5;
    int lane = threadIdx.x & 31;
    int pair = blockIdx.x * (blockDim.x >> 5) + wid;
    if (pair >= B * O) return;
    int idx = pair * VO + lane;

    float s;
    if (which == 0) {
        const float* pp = g_S0part + (size_t)pair * VO + lane;
        const size_t stride = (size_t)B * O * VO;
        float acc = 0.f;
#pragma unroll 8
        for (int k = 0; k < NIBLK; k++)
            acc += __ldcs(pp + (size_t)k * stride);
        s = acc * (1.0f / (float)O);
    } else if (which == 1) {
        s = g_S1[idx];
    } else {
        s = g_S2[idx];
    }

    float sq = s * s;
#pragma unroll
    for (int off = 16; off; off >>= 1)
        sq += __shfl_xor_sync(0xffffffffu, sq, off);

    float scale = (sq / (1.0f + sq)) * rsqrtf(sq + 1e-8f);
    float v = s * scale;

    if (which == 0)      g_Vacc[idx] = v;
    else if (which == 1) g_Vacc[idx] += v;
    else                 out[idx] = v;
}

// ---------------------------------------------------------------------------
extern "C" void kernel_launch(void* const* d_in, const int* in_sizes, int n_in,
                              void* d_out, int out_size) {
    const float* x;
    const float* W;
    if (in_sizes[0] == B * I * VI) {
        x = (const float*)d_in[0];
        W = (const float*)d_in[1];
    } else {
        x = (const float*)d_in[1];
        W = (const float*)d_in[0];
    }
    float* out = (float*)d_out;

    zero_kernel<<<(B * O * VO + 255) / 256, 256>>>();

    // P0: u_hat (fp16) via mma.sync + fused S0 partials
    p0_mma<<<dim3(NIBLK, O / 8), 256>>>(W, x);

    // Iteration 0: reduce S0 partials + squash
    kv_kernel<<<64, 1024>>>(0, out);   // v0 = squash(S0/64); Vacc = v0

    // Iteration 1: logits = u_hat . v0   (raw launch idx 5 -> ncu target)
    p1_kernel<<<2048, 64>>>(1);
    kv_kernel<<<64, 1024>>>(1, out);   // v1 = squash(S1); Vacc = v0 + v1

    // Iteration 2: logits = u_hat . (v0 + v1)
    p1_kernel<<<2048, 64>>>(2);
    kv_kernel<<<64, 1024>>>(2, out);   // out = squash(S2)
}

// round 14
// speedup vs baseline: 1.5291x; 1.1117x over previous
#include <cuda_runtime.h>
#include <cuda_fp16.h>
#include <math.h>

// Problem constants
#define B  32
#define O  64
#define I  2048
#define VO 32
#define VI 16

#define ITER 8            // i's per p0 CTA
#define NIBLK (I / ITER)  // 256 i-blocks

typedef unsigned long long u64;

// Scratch (device globals: no allocation allowed)
__device__ __half g_uhat[(size_t)B * I * O * VO];          // fp16, 256 MB
__device__ float g_S0part[(size_t)NIBLK * B * O * VO];     // 67 MB partial S0
__device__ float g_S1[B * O * VO];
__device__ float g_S2[B * O * VO];
__device__ float g_Vacc[B * O * VO];                       // v0, then v0+v1

// ---------------------------------------------------------------------------
// helpers
// ---------------------------------------------------------------------------
__device__ __forceinline__ unsigned int smem_u32(const void* p) {
    return (unsigned int)__cvta_generic_to_shared(p);
}
__device__ __forceinline__ void mma_16816(float* d, const unsigned int* a,
                                          const unsigned int* b) {
    asm volatile(
        "mma.sync.aligned.m16n8k16.row.col.f32.f16.f16.f32 "
        "{%0,%1,%2,%3},{%4,%5,%6,%7},{%8,%9},{%0,%1,%2,%3};"
        : "+f"(d[0]), "+f"(d[1]), "+f"(d[2]), "+f"(d[3])
        : "r"(a[0]), "r"(a[1]), "r"(a[2]), "r"(a[3]), "r"(b[0]), "r"(b[1]));
}
// NON-trans ldmatrix: SMEM rows are n (=v), cols are k (=u) -> B fragment
__device__ __forceinline__ void ldmx2(unsigned int& b0, unsigned int& b1,
                                      unsigned int saddr) {
    asm volatile("ldmatrix.sync.aligned.m8n8.x2.shared.b16 {%0,%1},[%2];"
                 : "=r"(b0), "=r"(b1) : "r"(saddr));
}
__device__ __forceinline__ unsigned int pack_h(float a, float b) {
    __half2 p = __halves2half2(__float2half_rn(a), __float2half_rn(b));
    return *(unsigned int*)&p;
}
__device__ __forceinline__ unsigned int pack_l(float a, float b, unsigned int hp) {
    float2 hf = __half22float2(*(__half2*)&hp);
    __half2 p = __halves2half2(__float2half_rn(a - hf.x), __float2half_rn(b - hf.y));
    return *(unsigned int*)&p;
}

// ---------------------------------------------------------------------------
// Zero the atomic accumulators (graph replays reuse scratch)
// ---------------------------------------------------------------------------
__global__ void zero_kernel() {
    int idx = blockIdx.x * blockDim.x + threadIdx.x;
    if (idx < B * O * VO) {
        g_S1[idx] = 0.0f;
        g_S2[idx] = 0.0f;
    }
}

// ---------------------------------------------------------------------------
// P0 (tensor cores, mma.sync, amortized, fused S0 partials) — R12 proven.
// ---------------------------------------------------------------------------
__global__ void __launch_bounds__(256) p0_mma(const float* __restrict__ W,
                                              const float* __restrict__ x) {
    __shared__ __half Whs[8 * 32 * 24];  // 12 KB  per-warp W-hi tile
    __shared__ __half Wls[8 * 32 * 24];  // 12 KB  per-warp W-lo tile
    __shared__ float  Xs[32 * 24];       //  3 KB  x fp32 (padded rows)
    __shared__ __half Dout[32 * 264];    // 16.5 KB output staging (padded)

    const int iblk = blockIdx.x;
    const int i0  = iblk * ITER;
    const int o0  = blockIdx.y * 8;
    const int tid = threadIdx.x;
    const int wid = tid >> 5;
    const int lane = tid & 31;

    const int gid = lane >> 2, tig = lane & 3;
    const int lr = lane & 7, sel = (lane >> 3) & 1;

    const float4* wbase = (const float4*)(W + ((size_t)(o0 + wid) * I + i0) * 512);
    const int xb = tid >> 2, xq = tid & 3;

    float facc[4][8];
#pragma unroll
    for (int j = 0; j < 4; j++)
#pragma unroll
        for (int e = 0; e < 8; e++) facc[j][e] = 0.f;

    // ---- prologue: prefetch i0 ----
    float4 w4[4];
#pragma unroll
    for (int j = 0; j < 4; j++) w4[j] = wbase[j * 32 + lane];
    float4 x4;
    if (tid < 128)
        x4 = *(const float4*)(x + ((size_t)xb * I + i0) * VI + xq * 4);

    for (int it = 0; it < ITER; it++) {
        const int i = i0 + it;

        // ---- stage from prefetch regs ----
#pragma unroll
        for (int j = 0; j < 4; j++) {
            int c = j * 32 + lane;
            int v = c >> 2, q = c & 3;
            unsigned int h0 = pack_h(w4[j].x, w4[j].y);
            unsigned int h1 = pack_h(w4[j].z, w4[j].w);
            unsigned int l0 = pack_l(w4[j].x, w4[j].y, h0);
            unsigned int l1 = pack_l(w4[j].z, w4[j].w, h1);
            *(uint2*)&Whs[(wid * 32 + v) * 24 + q * 4] = make_uint2(h0, h1);
            *(uint2*)&Wls[(wid * 32 + v) * 24 + q * 4] = make_uint2(l0, l1);
        }
        if (tid < 128)
            *(float4*)&Xs[xb * 24 + xq * 4] = x4;

        // ---- prefetch next i ----
        if (it + 1 < ITER) {
            const float4* wb2 = wbase + (size_t)(it + 1) * 128;
#pragma unroll
            for (int j = 0; j < 4; j++) w4[j] = wb2[j * 32 + lane];
            if (tid < 128)
                x4 = *(const float4*)(x + ((size_t)xb * I + (i + 1)) * VI + xq * 4);
        }
        __syncthreads();

        // ---- A fragments (proven R9 mapping) ----
        unsigned int Ah[2][4], Al[2][4];
#pragma unroll
        for (int mt = 0; mt < 2; mt++) {
            int r0 = gid + mt * 16, r1 = r0 + 8;
            float2 x00 = *(float2*)&Xs[r0 * 24 + 2 * tig];
            float2 x01 = *(float2*)&Xs[r0 * 24 + 2 * tig + 8];
            float2 x10 = *(float2*)&Xs[r1 * 24 + 2 * tig];
            float2 x11 = *(float2*)&Xs[r1 * 24 + 2 * tig + 8];
            Ah[mt][0] = pack_h(x00.x, x00.y);
            Ah[mt][1] = pack_h(x10.x, x10.y);
            Ah[mt][2] = pack_h(x01.x, x01.y);
            Ah[mt][3] = pack_h(x11.x, x11.y);
            Al[mt][0] = pack_l(x00.x, x00.y, Ah[mt][0]);
            Al[mt][1] = pack_l(x10.x, x10.y, Ah[mt][1]);
            Al[mt][2] = pack_l(x01.x, x01.y, Ah[mt][2]);
            Al[mt][3] = pack_l(x11.x, x11.y, Ah[mt][3]);
        }

        // ---- MMA + epilogue STS into Dout ----
#pragma unroll
        for (int nt = 0; nt < 4; nt++) {
            unsigned int bh[2], bl[2];
            ldmx2(bh[0], bh[1],
                  smem_u32(&Whs[(wid * 32 + nt * 8 + lr) * 24 + sel * 8]));
            ldmx2(bl[0], bl[1],
                  smem_u32(&Wls[(wid * 32 + nt * 8 + lr) * 24 + sel * 8]));
#pragma unroll
            for (int mt = 0; mt < 2; mt++) {
                float d[4] = {0.f, 0.f, 0.f, 0.f};
                mma_16816(d, Ah[mt], bh);
                mma_16816(d, Al[mt], bh);
                mma_16816(d, Ah[mt], bl);

                int v  = 2 * tig + nt * 8;
                int b0 = gid + mt * 16;
                *(unsigned int*)&Dout[b0 * 264 + wid * 32 + v] = pack_h(d[0], d[1]);
                *(unsigned int*)&Dout[(b0 + 8) * 264 + wid * 32 + v] = pack_h(d[2], d[3]);
            }
        }
        __syncthreads();

        // ---- coalesced store + S0 partial accumulation ----
#pragma unroll
        for (int j = 0; j < 4; j++) {
            int c = j * 256 + tid;
            int b = c >> 5, k = c & 31;
            uint4 val = *(uint4*)((char*)Dout + b * 528 + k * 16);
            __half* dst = g_uhat + (((size_t)b * I + i) * O + o0) * VO + k * 8;
            __stcs((uint4*)dst, val);

            float2 f0 = __half22float2(*(const __half2*)&val.x);
            float2 f1 = __half22float2(*(const __half2*)&val.y);
            float2 f2 = __half22float2(*(const __half2*)&val.z);
            float2 f3 = __half22float2(*(const __half2*)&val.w);
            facc[j][0] += f0.x; facc[j][1] += f0.y;
            facc[j][2] += f1.x; facc[j][3] += f1.y;
            facc[j][4] += f2.x; facc[j][5] += f2.y;
            facc[j][6] += f3.x; facc[j][7] += f3.y;
        }
    }

    // ---- flush S0 partials: part[iblk][b][o][v], coalesced ----
#pragma unroll
    for (int j = 0; j < 4; j++) {
        int c = j * 256 + tid;
        int b = c >> 5, k = c & 31;
        float* dst = g_S0part +
            (((size_t)iblk * B + b) * O + (o0 + (k >> 2))) * VO + (k & 3) * 8;
        *(float4*)dst       = make_float4(facc[j][0], facc[j][1], facc[j][2], facc[j][3]);
        *(float4*)(dst + 4) = make_float4(facc[j][4], facc[j][5], facc[j][6], facc[j][7]);
    }
}

// ---------------------------------------------------------------------------
// P1/P2 v4: warp-pair routing pass, software-pipelined, 1 barrier/iter.
// CTA = 64 threads = 2 warps = one (b, 32-i chunk). Lane owns a single o.
// Loads for iteration ic+1 issue BEFORE ic's softmax (hides DRAM latency).
// Softmax without max-subtraction (logits |d| <~ 3, exp can't overflow):
// single sum-reduce + one smem exchange + one __syncthreads per iteration.
// ---------------------------------------------------------------------------
__global__ void __launch_bounds__(64) p1_kernel(int pass) {
    __shared__ float wsum[2];

    const int pairid = blockIdx.x;
    const int half = threadIdx.x >> 5;
    const int lane = threadIdx.x & 31;
    const int b = pairid >> 6;             // 32 b's
    const int i0 = (pairid & 63) * 32;     // 64 chunks of 32 i's
    const int o = half * 32 + lane;
    float* Sout = (pass == 1) ? g_S1 : g_S2;

    // Vacc row for this o (fp32, 32 regs)
    float va[VO];
    {
        const float4* vp = (const float4*)(g_Vacc + (size_t)(b * O + o) * VO);
#pragma unroll
        for (int j = 0; j < 8; j++) {
            float4 t4 = vp[j];
            va[4 * j + 0] = t4.x; va[4 * j + 1] = t4.y;
            va[4 * j + 2] = t4.z; va[4 * j + 3] = t4.w;
        }
    }

    float sa[VO];
#pragma unroll
    for (int v = 0; v < VO; v++) sa[v] = 0.f;

    // row base (in uint4): ((b*I+i)*O + o) * 4
    const uint4* up = (const uint4*)g_uhat;
    size_t rbase = (((size_t)b * I + i0) * O + o) * 4;
    const size_t rstride = (size_t)O * 4;   // per-i

    // prologue: load i0
    uint4 c0 = __ldcs(up + rbase + 0);
    uint4 c1 = __ldcs(up + rbase + 1);
    uint4 c2 = __ldcs(up + rbase + 2);
    uint4 c3 = __ldcs(up + rbase + 3);

    for (int ic = 0; ic < 32; ic++) {
        // ---- prefetch next iteration's row ----
        uint4 n0, n1, n2, n3;
        if (ic + 1 < 32) {
            size_t nb = rbase + (size_t)(ic + 1) * rstride;
            n0 = __ldcs(up + nb + 0);
            n1 = __ldcs(up + nb + 1);
            n2 = __ldcs(up + nb + 2);
            n3 = __ldcs(up + nb + 3);
        }

        unsigned int r[16] = {c0.x, c0.y, c0.z, c0.w, c1.x, c1.y, c1.z, c1.w,
                              c2.x, c2.y, c2.z, c2.w, c3.x, c3.y, c3.z, c3.w};

        float d = 0.f;
#pragma unroll
        for (int j = 0; j < 16; j++) {
            float2 f = __half22float2(*(const __half2*)&r[j]);
            d = fmaf(f.x, va[2 * j + 0], d);
            d = fmaf(f.y, va[2 * j + 1], d);
        }

        // softmax over 64 o's without max-shift (|d| <~ 3): one reduce+barrier
        float e = __expf(d);
        float es = e;
#pragma unroll
        for (int off = 16; off; off >>= 1)
            es += __shfl_xor_sync(0xffffffffu, es, off);
        if (lane == 0) wsum[half] = es;
        __syncthreads();
        float c = e * __frcp_rn(wsum[0] + wsum[1]);
        __syncthreads();   // wsum consumed before next iteration overwrites

        // ---- accumulate ----
#pragma unroll
        for (int j = 0; j < 16; j++) {
            float2 f = __half22float2(*(const __half2*)&r[j]);
            sa[2 * j + 0] = fmaf(c, f.x, sa[2 * j + 0]);
            sa[2 * j + 1] = fmaf(c, f.y, sa[2 * j + 1]);
        }

        c0 = n0; c1 = n1; c2 = n2; c3 = n3;
    }

    float* sp = Sout + (size_t)(b * O + o) * VO;
#pragma unroll
    for (int v = 0; v < VO; v++)
        atomicAdd(&sp[v], sa[v]);
}

// ---------------------------------------------------------------------------
// Squash. which==0: reduce g_S0part over 256 i-blocks, v0=squash(S0/64),
//                   Vacc=v0.
//         which==1: v1=squash(S1), Vacc+=v1.
//         which==2: out=squash(S2).
// ---------------------------------------------------------------------------
__global__ void kv_kernel(int which, float* __restrict__ out) {
    int wid = threadIdx.x >> 5;
    int lane = threadIdx.x & 31;
    int pair = blockIdx.x * (blockDim.x >> 5) + wid;
    if (pair >= B * O) return;
    int idx = pair * VO + lane;

    float s;
    if (which == 0) {
        const float* pp = g_S0part + (size_t)pair * VO + lane;
        const size_t stride = (size_t)B * O * VO;
        float acc = 0.f;
#pragma unroll 8
        for (int k = 0; k < NIBLK; k++)
            acc += __ldcs(pp + (size_t)k * stride);
        s = acc * (1.0f / (float)O);
    } else if (which == 1) {
        s = g_S1[idx];
    } else {
        s = g_S2[idx];
    }

    float sq = s * s;
#pragma unroll
    for (int off = 16; off; off >>= 1)
        sq += __shfl_xor_sync(0xffffffffu, sq, off);

    float scale = (sq / (1.0f + sq)) * rsqrtf(sq + 1e-8f);
    float v = s * scale;

    if (which == 0)      g_Vacc[idx] = v;
    else if (which == 1) g_Vacc[idx] += v;
    else                 out[idx] = v;
}

// ---------------------------------------------------------------------------
extern "C" void kernel_launch(void* const* d_in, const int* in_sizes, int n_in,
                              void* d_out, int out_size) {
    const float* x;
    const float* W;
    if (in_sizes[0] == B * I * VI) {
        x = (const float*)d_in[0];
        W = (const float*)d_in[1];
    } else {
        x = (const float*)d_in[1];
        W = (const float*)d_in[0];
    }
    float* out = (float*)d_out;

    zero_kernel<<<(B * O * VO + 255) / 256, 256>>>();

    // P0: u_hat (fp16) via mma.sync + fused S0 partials
    p0_mma<<<dim3(NIBLK, O / 8), 256>>>(W, x);

    // Iteration 0: reduce S0 partials + squash
    kv_kernel<<<64, 1024>>>(0, out);   // v0 = squash(S0/64); Vacc = v0

    // Iteration 1: logits = u_hat . v0   (raw launch idx 5 -> ncu target)
    p1_kernel<<<2048, 64>>>(1);
    kv_kernel<<<64, 1024>>>(1, out);   // v1 = squash(S1); Vacc = v0 + v1

    // Iteration 2: logits = u_hat . (v0 + v1)
    p1_kernel<<<2048, 64>>>(2);
    kv_kernel<<<64, 1024>>>(2, out);   // out = squash(S2)
}

// round 15
// speedup vs baseline: 1.5382x; 1.0060x over previous
#include <cuda_runtime.h>
#include <cuda_fp16.h>
#include <math.h>

// Problem constants
#define B  32
#define O  64
#define I  2048
#define VO 32
#define VI 16

#define ITER 8            // i's per p0 CTA
#define NIBLK (I / ITER)  // 256 i-blocks

typedef unsigned long long u64;

// Scratch (device globals: no allocation allowed)
__device__ __half g_uhat[(size_t)B * I * O * VO];          // fp16, 256 MB
__device__ float g_S0part[(size_t)NIBLK * B * O * VO];     // 67 MB partial S0
__device__ float g_S1[B * O * VO];
__device__ float g_S2[B * O * VO];
__device__ float g_Vacc[B * O * VO];                       // v0, then v0+v1

// ---------------------------------------------------------------------------
// helpers
// ---------------------------------------------------------------------------
__device__ __forceinline__ unsigned int smem_u32(const void* p) {
    return (unsigned int)__cvta_generic_to_shared(p);
}
__device__ __forceinline__ void mma_16816(float* d, const unsigned int* a,
                                          const unsigned int* b) {
    asm volatile(
        "mma.sync.aligned.m16n8k16.row.col.f32.f16.f16.f32 "
        "{%0,%1,%2,%3},{%4,%5,%6,%7},{%8,%9},{%0,%1,%2,%3};"
        : "+f"(d[0]), "+f"(d[1]), "+f"(d[2]), "+f"(d[3])
        : "r"(a[0]), "r"(a[1]), "r"(a[2]), "r"(a[3]), "r"(b[0]), "r"(b[1]));
}
// NON-trans ldmatrix: SMEM rows are n (=v), cols are k (=u) -> B fragment
__device__ __forceinline__ void ldmx2(unsigned int& b0, unsigned int& b1,
                                      unsigned int saddr) {
    asm volatile("ldmatrix.sync.aligned.m8n8.x2.shared.b16 {%0,%1},[%2];"
                 : "=r"(b0), "=r"(b1) : "r"(saddr));
}
__device__ __forceinline__ unsigned int pack_h(float a, float b) {
    __half2 p = __halves2half2(__float2half_rn(a), __float2half_rn(b));
    return *(unsigned int*)&p;
}
__device__ __forceinline__ unsigned int pack_l(float a, float b, unsigned int hp) {
    float2 hf = __half22float2(*(__half2*)&hp);
    __half2 p = __halves2half2(__float2half_rn(a - hf.x), __float2half_rn(b - hf.y));
    return *(unsigned int*)&p;
}

// ---------------------------------------------------------------------------
// Zero the atomic accumulators (graph replays reuse scratch)
// ---------------------------------------------------------------------------
__global__ void zero_kernel() {
    int idx = blockIdx.x * blockDim.x + threadIdx.x;
    if (idx < B * O * VO) {
        g_S1[idx] = 0.0f;
        g_S2[idx] = 0.0f;
    }
}

// ---------------------------------------------------------------------------
// P0 (tensor cores, mma.sync, amortized, fused S0 partials) — R12 proven.
// ---------------------------------------------------------------------------
__global__ void __launch_bounds__(256) p0_mma(const float* __restrict__ W,
                                              const float* __restrict__ x) {
    __shared__ __half Whs[8 * 32 * 24];  // 12 KB  per-warp W-hi tile
    __shared__ __half Wls[8 * 32 * 24];  // 12 KB  per-warp W-lo tile
    __shared__ float  Xs[32 * 24];       //  3 KB  x fp32 (padded rows)
    __shared__ __half Dout[32 * 264];    // 16.5 KB output staging (padded)

    const int iblk = blockIdx.x;
    const int i0  = iblk * ITER;
    const int o0  = blockIdx.y * 8;
    const int tid = threadIdx.x;
    const int wid = tid >> 5;
    const int lane = tid & 31;

    const int gid = lane >> 2, tig = lane & 3;
    const int lr = lane & 7, sel = (lane >> 3) & 1;

    const float4* wbase = (const float4*)(W + ((size_t)(o0 + wid) * I + i0) * 512);
    const int xb = tid >> 2, xq = tid & 3;

    float facc[4][8];
#pragma unroll
    for (int j = 0; j < 4; j++)
#pragma unroll
        for (int e = 0; e < 8; e++) facc[j][e] = 0.f;

    // ---- prologue: prefetch i0 ----
    float4 w4[4];
#pragma unroll
    for (int j = 0; j < 4; j++) w4[j] = wbase[j * 32 + lane];
    float4 x4;
    if (tid < 128)
        x4 = *(const float4*)(x + ((size_t)xb * I + i0) * VI + xq * 4);

    for (int it = 0; it < ITER; it++) {
        const int i = i0 + it;

        // ---- stage from prefetch regs ----
#pragma unroll
        for (int j = 0; j < 4; j++) {
            int c = j * 32 + lane;
            int v = c >> 2, q = c & 3;
            unsigned int h0 = pack_h(w4[j].x, w4[j].y);
            unsigned int h1 = pack_h(w4[j].z, w4[j].w);
            unsigned int l0 = pack_l(w4[j].x, w4[j].y, h0);
            unsigned int l1 = pack_l(w4[j].z, w4[j].w, h1);
            *(uint2*)&Whs[(wid * 32 + v) * 24 + q * 4] = make_uint2(h0, h1);
            *(uint2*)&Wls[(wid * 32 + v) * 24 + q * 4] = make_uint2(l0, l1);
        }
        if (tid < 128)
            *(float4*)&Xs[xb * 24 + xq * 4] = x4;

        // ---- prefetch next i ----
        if (it + 1 < ITER) {
            const float4* wb2 = wbase + (size_t)(it + 1) * 128;
#pragma unroll
            for (int j = 0; j < 4; j++) w4[j] = wb2[j * 32 + lane];
            if (tid < 128)
                x4 = *(const float4*)(x + ((size_t)xb * I + (i + 1)) * VI + xq * 4);
        }
        __syncthreads();

        // ---- A fragments (proven R9 mapping) ----
        unsigned int Ah[2][4], Al[2][4];
#pragma unroll
        for (int mt = 0; mt < 2; mt++) {
            int r0 = gid + mt * 16, r1 = r0 + 8;
            float2 x00 = *(float2*)&Xs[r0 * 24 + 2 * tig];
            float2 x01 = *(float2*)&Xs[r0 * 24 + 2 * tig + 8];
            float2 x10 = *(float2*)&Xs[r1 * 24 + 2 * tig];
            float2 x11 = *(float2*)&Xs[r1 * 24 + 2 * tig + 8];
            Ah[mt][0] = pack_h(x00.x, x00.y);
            Ah[mt][1] = pack_h(x10.x, x10.y);
            Ah[mt][2] = pack_h(x01.x, x01.y);
            Ah[mt][3] = pack_h(x11.x, x11.y);
            Al[mt][0] = pack_l(x00.x, x00.y, Ah[mt][0]);
            Al[mt][1] = pack_l(x10.x, x10.y, Ah[mt][1]);
            Al[mt][2] = pack_l(x01.x, x01.y, Ah[mt][2]);
            Al[mt][3] = pack_l(x11.x, x11.y, Ah[mt][3]);
        }

        // ---- MMA + epilogue STS into Dout ----
#pragma unroll
        for (int nt = 0; nt < 4; nt++) {
            unsigned int bh[2], bl[2];
            ldmx2(bh[0], bh[1],
                  smem_u32(&Whs[(wid * 32 + nt * 8 + lr) * 24 + sel * 8]));
            ldmx2(bl[0], bl[1],
                  smem_u32(&Wls[(wid * 32 + nt * 8 + lr) * 24 + sel * 8]));
#pragma unroll
            for (int mt = 0; mt < 2; mt++) {
                float d[4] = {0.f, 0.f, 0.f, 0.f};
                mma_16816(d, Ah[mt], bh);
                mma_16816(d, Al[mt], bh);
                mma_16816(d, Ah[mt], bl);

                int v  = 2 * tig + nt * 8;
                int b0 = gid + mt * 16;
                *(unsigned int*)&Dout[b0 * 264 + wid * 32 + v] = pack_h(d[0], d[1]);
                *(unsigned int*)&Dout[(b0 + 8) * 264 + wid * 32 + v] = pack_h(d[2], d[3]);
            }
        }
        __syncthreads();

        // ---- coalesced store + S0 partial accumulation ----
#pragma unroll
        for (int j = 0; j < 4; j++) {
            int c = j * 256 + tid;
            int b = c >> 5, k = c & 31;
            uint4 val = *(uint4*)((char*)Dout + b * 528 + k * 16);
            __half* dst = g_uhat + (((size_t)b * I + i) * O + o0) * VO + k * 8;
            __stcs((uint4*)dst, val);

            float2 f0 = __half22float2(*(const __half2*)&val.x);
            float2 f1 = __half22float2(*(const __half2*)&val.y);
            float2 f2 = __half22float2(*(const __half2*)&val.z);
            float2 f3 = __half22float2(*(const __half2*)&val.w);
            facc[j][0] += f0.x; facc[j][1] += f0.y;
            facc[j][2] += f1.x; facc[j][3] += f1.y;
            facc[j][4] += f2.x; facc[j][5] += f2.y;
            facc[j][6] += f3.x; facc[j][7] += f3.y;
        }
    }

    // ---- flush S0 partials: part[iblk][b][o][v], coalesced ----
#pragma unroll
    for (int j = 0; j < 4; j++) {
        int c = j * 256 + tid;
        int b = c >> 5, k = c & 31;
        float* dst = g_S0part +
            (((size_t)iblk * B + b) * O + (o0 + (k >> 2))) * VO + (k & 3) * 8;
        *(float4*)dst       = make_float4(facc[j][0], facc[j][1], facc[j][2], facc[j][3]);
        *(float4*)(dst + 4) = make_float4(facc[j][4], facc[j][5], facc[j][6], facc[j][7]);
    }
}

// ---------------------------------------------------------------------------
// P1/P2 v5: (o, v-half) split routing pass. CTA = 128 thr = 4 warps = one
// (b, 32-i chunk). Thread owns o = warp*16 + (lane>>1), v-half = lane&1
// -> ~70 regs (va16+sa16+row8+pf8) -> ~2x occupancy vs v4.
// Warp load = 16 rows x 64B = 1KB contiguous per i. Dot completed via one
// shfl_xor(1) with the partner lane. Softmax (no max-shift; |d|<~3):
// warp reduce (lanes duplicated => x0.5) + 4-warp smem exchange,
// double-buffered wsum -> ONE barrier per iteration. Next-i row prefetched
// before the softmax chain (hides DRAM latency).
// ---------------------------------------------------------------------------
__global__ void __launch_bounds__(128) p1_kernel(int pass) {
    __shared__ float wsum[2][4];

    const int cta = blockIdx.x;
    const int tid = threadIdx.x;
    const int warp = tid >> 5;
    const int lane = tid & 31;
    const int b = cta >> 6;               // 32 b's
    const int i0 = (cta & 63) * 32;       // 64 chunks of 32 i's
    const int o = warp * 16 + (lane >> 1);
    const int vh = lane & 1;              // v in [vh*16, vh*16+16)
    float* Sout = (pass == 1) ? g_S1 : g_S2;

    // Vacc half-row for this (o, vh): 16 floats
    float va[16];
    {
        const float4* vp = (const float4*)(g_Vacc + (size_t)(b * O + o) * VO + vh * 16);
#pragma unroll
        for (int j = 0; j < 4; j++) {
            float4 t4 = vp[j];
            va[4 * j + 0] = t4.x; va[4 * j + 1] = t4.y;
            va[4 * j + 2] = t4.z; va[4 * j + 3] = t4.w;
        }
    }

    float sa[16];
#pragma unroll
    for (int v = 0; v < 16; v++) sa[v] = 0.f;

    // half-row base (in uint4): ((b*I+i)*O + o)*4 + vh*2
    const uint4* up = (const uint4*)g_uhat;
    size_t rbase = (((size_t)b * I + i0) * O + o) * 4 + (size_t)vh * 2;
    const size_t rstride = (size_t)O * 4;   // per-i

    // prologue: load i0 half-row (32B)
    uint4 c0 = __ldcs(up + rbase + 0);
    uint4 c1 = __ldcs(up + rbase + 1);

    for (int ic = 0; ic < 32; ic++) {
        // ---- prefetch next iteration's half-row ----
        uint4 n0, n1;
        if (ic + 1 < 32) {
            size_t nb = rbase + (size_t)(ic + 1) * rstride;
            n0 = __ldcs(up + nb + 0);
            n1 = __ldcs(up + nb + 1);
        }

        unsigned int r[8] = {c0.x, c0.y, c0.z, c0.w, c1.x, c1.y, c1.z, c1.w};

        // half-dot over 16 v's, completed with the partner lane
        float d = 0.f;
#pragma unroll
        for (int j = 0; j < 8; j++) {
            float2 f = __half22float2(*(const __half2*)&r[j]);
            d = fmaf(f.x, va[2 * j + 0], d);
            d = fmaf(f.y, va[2 * j + 1], d);
        }
        d += __shfl_xor_sync(0xffffffffu, d, 1);   // full dot, both lanes hold it

        // softmax over 64 o's, no max-shift (|d| <~ 3)
        float e = __expf(d);
        float es = e;
#pragma unroll
        for (int off = 16; off; off >>= 1)
            es += __shfl_xor_sync(0xffffffffu, es, off);  // = 2 * sum of 16 o's
        if (lane == 0) wsum[ic & 1][warp] = es;
        __syncthreads();
        float tot = (wsum[ic & 1][0] + wsum[ic & 1][1] +
                     wsum[ic & 1][2] + wsum[ic & 1][3]) * 0.5f;
        float c = e * __frcp_rn(tot);
        // (no second barrier: slot ic&1 isn't rewritten until ic+2, after
        //  the ic+1 barrier, by which time all reads here are done)

        // ---- accumulate ----
#pragma unroll
        for (int j = 0; j < 8; j++) {
            float2 f = __half22float2(*(const __half2*)&r[j]);
            sa[2 * j + 0] = fmaf(c, f.x, sa[2 * j + 0]);
            sa[2 * j + 1] = fmaf(c, f.y, sa[2 * j + 1]);
        }

        c0 = n0; c1 = n1;
    }

    float* sp = Sout + (size_t)(b * O + o) * VO + vh * 16;
#pragma unroll
    for (int v = 0; v < 16; v++)
        atomicAdd(&sp[v], sa[v]);
}

// ---------------------------------------------------------------------------
// Squash. which==0: reduce g_S0part over 256 i-blocks, v0=squash(S0/64),
//                   Vacc=v0.
//         which==1: v1=squash(S1), Vacc+=v1.
//         which==2: out=squash(S2).
// ---------------------------------------------------------------------------
__global__ void kv_kernel(int which, float* __restrict__ out) {
    int wid = threadIdx.x >> 5;
    int lane = threadIdx.x & 31;
    int pair = blockIdx.x * (blockDim.x >> 5) + wid;
    if (pair >= B * O) return;
    int idx = pair * VO + lane;

    float s;
    if (which == 0) {
        const float* pp = g_S0part + (size_t)pair * VO + lane;
        const size_t stride = (size_t)B * O * VO;
        float acc = 0.f;
#pragma unroll 8
        for (int k = 0; k < NIBLK; k++)
            acc += __ldcs(pp + (size_t)k * stride);
        s = acc * (1.0f / (float)O);
    } else if (which == 1) {
        s = g_S1[idx];
    } else {
        s = g_S2[idx];
    }

    float sq = s * s;
#pragma unroll
    for (int off = 16; off; off >>= 1)
        sq += __shfl_xor_sync(0xffffffffu, sq, off);

    float scale = (sq / (1.0f + sq)) * rsqrtf(sq + 1e-8f);
    float v = s * scale;

    if (which == 0)      g_Vacc[idx] = v;
    else if (which == 1) g_Vacc[idx] += v;
    else                 out[idx] = v;
}

// ---------------------------------------------------------------------------
extern "C" void kernel_launch(void* const* d_in, const int* in_sizes, int n_in,
                              void* d_out, int out_size) {
    const float* x;
    const float* W;
    if (in_sizes[0] == B * I * VI) {
        x = (const float*)d_in[0];
        W = (const float*)d_in[1];
    } else {
        x = (const float*)d_in[1];
        W = (const float*)d_in[0];
    }
    float* out = (float*)d_out;

    zero_kernel<<<(B * O * VO + 255) / 256, 256>>>();

    // P0: u_hat (fp16) via mma.sync + fused S0 partials
    p0_mma<<<dim3(NIBLK, O / 8), 256>>>(W, x);

    // Iteration 0: reduce S0 partials + squash
    kv_kernel<<<64, 1024>>>(0, out);   // v0 = squash(S0/64); Vacc = v0

    // Iteration 1: logits = u_hat . v0   (raw launch idx 5 -> ncu target)
    p1_kernel<<<2048, 128>>>(1);
    kv_kernel<<<64, 1024>>>(1, out);   // v1 = squash(S1); Vacc = v0 + v1

    // Iteration 2: logits = u_hat . (v0 + v1)
    p1_kernel<<<2048, 128>>>(2);
    kv_kernel<<<64, 1024>>>(2, out);   // out = squash(S2)
}

// round 16
// speedup vs baseline: 1.5766x; 1.0250x over previous
#include <cuda_runtime.h>
#include <cuda_fp16.h>
#include <math.h>

// Problem constants
#define B  32
#define O  64
#define I  2048
#define VO 32
#define VI 16

#define ITER 8            // i's per p0 CTA
#define NIBLK (I / ITER)  // 256 i-blocks

typedef unsigned long long u64;

// Scratch (device globals: no allocation allowed)
__device__ __half g_uhat[(size_t)B * I * O * VO];          // fp16, 256 MB
__device__ float g_S0part[(size_t)NIBLK * B * O * VO];     // 67 MB partial S0
__device__ float g_S1[B * O * VO];
__device__ float g_S2[B * O * VO];
__device__ float g_Vacc[B * O * VO];                       // v0, then v0+v1

// ---------------------------------------------------------------------------
// helpers
// ---------------------------------------------------------------------------
__device__ __forceinline__ unsigned int smem_u32(const void* p) {
    return (unsigned int)__cvta_generic_to_shared(p);
}
__device__ __forceinline__ void mma_16816(float* d, const unsigned int* a,
                                          const unsigned int* b) {
    asm volatile(
        "mma.sync.aligned.m16n8k16.row.col.f32.f16.f16.f32 "
        "{%0,%1,%2,%3},{%4,%5,%6,%7},{%8,%9},{%0,%1,%2,%3};"
        : "+f"(d[0]), "+f"(d[1]), "+f"(d[2]), "+f"(d[3])
        : "r"(a[0]), "r"(a[1]), "r"(a[2]), "r"(a[3]), "r"(b[0]), "r"(b[1]));
}
// NON-trans ldmatrix: SMEM rows are n (=v), cols are k (=u) -> B fragment
__device__ __forceinline__ void ldmx2(unsigned int& b0, unsigned int& b1,
                                      unsigned int saddr) {
    asm volatile("ldmatrix.sync.aligned.m8n8.x2.shared.b16 {%0,%1},[%2];"
                 : "=r"(b0), "=r"(b1) : "r"(saddr));
}
__device__ __forceinline__ unsigned int pack_h(float a, float b) {
    __half2 p = __halves2half2(__float2half_rn(a), __float2half_rn(b));
    return *(unsigned int*)&p;
}
__device__ __forceinline__ unsigned int pack_l(float a, float b, unsigned int hp) {
    float2 hf = __half22float2(*(__half2*)&hp);
    __half2 p = __halves2half2(__float2half_rn(a - hf.x), __float2half_rn(b - hf.y));
    return *(unsigned int*)&p;
}

// ---------------------------------------------------------------------------
// Zero the atomic accumulators (graph replays reuse scratch)
// ---------------------------------------------------------------------------
__global__ void zero_kernel() {
    int idx = blockIdx.x * blockDim.x + threadIdx.x;
    if (idx < B * O * VO) {
        g_S1[idx] = 0.0f;
        g_S2[idx] = 0.0f;
    }
}

// ---------------------------------------------------------------------------
// P0 (tensor cores, mma.sync, amortized, fused S0 partials) — R12 proven.
// ---------------------------------------------------------------------------
__global__ void __launch_bounds__(256) p0_mma(const float* __restrict__ W,
                                              const float* __restrict__ x) {
    __shared__ __half Whs[8 * 32 * 24];  // 12 KB  per-warp W-hi tile
    __shared__ __half Wls[8 * 32 * 24];  // 12 KB  per-warp W-lo tile
    __shared__ float  Xs[32 * 24];       //  3 KB  x fp32 (padded rows)
    __shared__ __half Dout[32 * 264];    // 16.5 KB output staging (padded)

    const int iblk = blockIdx.x;
    const int i0  = iblk * ITER;
    const int o0  = blockIdx.y * 8;
    const int tid = threadIdx.x;
    const int wid = tid >> 5;
    const int lane = tid & 31;

    const int gid = lane >> 2, tig = lane & 3;
    const int lr = lane & 7, sel = (lane >> 3) & 1;

    const float4* wbase = (const float4*)(W + ((size_t)(o0 + wid) * I + i0) * 512);
    const int xb = tid >> 2, xq = tid & 3;

    float facc[4][8];
#pragma unroll
    for (int j = 0; j < 4; j++)
#pragma unroll
        for (int e = 0; e < 8; e++) facc[j][e] = 0.f;

    // ---- prologue: prefetch i0 ----
    float4 w4[4];
#pragma unroll
    for (int j = 0; j < 4; j++) w4[j] = wbase[j * 32 + lane];
    float4 x4;
    if (tid < 128)
        x4 = *(const float4*)(x + ((size_t)xb * I + i0) * VI + xq * 4);

    for (int it = 0; it < ITER; it++) {
        const int i = i0 + it;

        // ---- stage from prefetch regs ----
#pragma unroll
        for (int j = 0; j < 4; j++) {
            int c = j * 32 + lane;
            int v = c >> 2, q = c & 3;
            unsigned int h0 = pack_h(w4[j].x, w4[j].y);
            unsigned int h1 = pack_h(w4[j].z, w4[j].w);
            unsigned int l0 = pack_l(w4[j].x, w4[j].y, h0);
            unsigned int l1 = pack_l(w4[j].z, w4[j].w, h1);
            *(uint2*)&Whs[(wid * 32 + v) * 24 + q * 4] = make_uint2(h0, h1);
            *(uint2*)&Wls[(wid * 32 + v) * 24 + q * 4] = make_uint2(l0, l1);
        }
        if (tid < 128)
            *(float4*)&Xs[xb * 24 + xq * 4] = x4;

        // ---- prefetch next i ----
        if (it + 1 < ITER) {
            const float4* wb2 = wbase + (size_t)(it + 1) * 128;
#pragma unroll
            for (int j = 0; j < 4; j++) w4[j] = wb2[j * 32 + lane];
            if (tid < 128)
                x4 = *(const float4*)(x + ((size_t)xb * I + (i + 1)) * VI + xq * 4);
        }
        __syncthreads();

        // ---- A fragments (proven R9 mapping) ----
        unsigned int Ah[2][4], Al[2][4];
#pragma unroll
        for (int mt = 0; mt < 2; mt++) {
            int r0 = gid + mt * 16, r1 = r0 + 8;
            float2 x00 = *(float2*)&Xs[r0 * 24 + 2 * tig];
            float2 x01 = *(float2*)&Xs[r0 * 24 + 2 * tig + 8];
            float2 x10 = *(float2*)&Xs[r1 * 24 + 2 * tig];
            float2 x11 = *(float2*)&Xs[r1 * 24 + 2 * tig + 8];
            Ah[mt][0] = pack_h(x00.x, x00.y);
            Ah[mt][1] = pack_h(x10.x, x10.y);
            Ah[mt][2] = pack_h(x01.x, x01.y);
            Ah[mt][3] = pack_h(x11.x, x11.y);
            Al[mt][0] = pack_l(x00.x, x00.y, Ah[mt][0]);
            Al[mt][1] = pack_l(x10.x, x10.y, Ah[mt][1]);
            Al[mt][2] = pack_l(x01.x, x01.y, Ah[mt][2]);
            Al[mt][3] = pack_l(x11.x, x11.y, Ah[mt][3]);
        }

        // ---- MMA + epilogue STS into Dout ----
#pragma unroll
        for (int nt = 0; nt < 4; nt++) {
            unsigned int bh[2], bl[2];
            ldmx2(bh[0], bh[1],
                  smem_u32(&Whs[(wid * 32 + nt * 8 + lr) * 24 + sel * 8]));
            ldmx2(bl[0], bl[1],
                  smem_u32(&Wls[(wid * 32 + nt * 8 + lr) * 24 + sel * 8]));
#pragma unroll
            for (int mt = 0; mt < 2; mt++) {
                float d[4] = {0.f, 0.f, 0.f, 0.f};
                mma_16816(d, Ah[mt], bh);
                mma_16816(d, Al[mt], bh);
                mma_16816(d, Ah[mt], bl);

                int v  = 2 * tig + nt * 8;
                int b0 = gid + mt * 16;
                *(unsigned int*)&Dout[b0 * 264 + wid * 32 + v] = pack_h(d[0], d[1]);
                *(unsigned int*)&Dout[(b0 + 8) * 264 + wid * 32 + v] = pack_h(d[2], d[3]);
            }
        }
        __syncthreads();

        // ---- coalesced store + S0 partial accumulation ----
#pragma unroll
        for (int j = 0; j < 4; j++) {
            int c = j * 256 + tid;
            int b = c >> 5, k = c & 31;
            uint4 val = *(uint4*)((char*)Dout + b * 528 + k * 16);
            __half* dst = g_uhat + (((size_t)b * I + i) * O + o0) * VO + k * 8;
            __stcs((uint4*)dst, val);

            float2 f0 = __half22float2(*(const __half2*)&val.x);
            float2 f1 = __half22float2(*(const __half2*)&val.y);
            float2 f2 = __half22float2(*(const __half2*)&val.z);
            float2 f3 = __half22float2(*(const __half2*)&val.w);
            facc[j][0] += f0.x; facc[j][1] += f0.y;
            facc[j][2] += f1.x; facc[j][3] += f1.y;
            facc[j][4] += f2.x; facc[j][5] += f2.y;
            facc[j][6] += f3.x; facc[j][7] += f3.y;
        }
    }

    // ---- flush S0 partials: part[iblk][b][o][v], coalesced ----
#pragma unroll
    for (int j = 0; j < 4; j++) {
        int c = j * 256 + tid;
        int b = c >> 5, k = c & 31;
        float* dst = g_S0part +
            (((size_t)iblk * B + b) * O + (o0 + (k >> 2))) * VO + (k & 3) * 8;
        *(float4*)dst       = make_float4(facc[j][0], facc[j][1], facc[j][2], facc[j][3]);
        *(float4*)(dst + 4) = make_float4(facc[j][4], facc[j][5], facc[j][6], facc[j][7]);
    }
}

// ---------------------------------------------------------------------------
// P1/P2 v6: (o, v-half) split + 4-i batching. CTA = 128 thr = 4 warps = one
// (b, 32-i chunk), 8 batches of 4 i's. Per batch: 8 independent uint4 loads
// (128B/thread in flight), 4 independent dots, 4 INTERLEAVED shuffle reduces
// (chain amortized 4x), ONE barrier (double-buffered wsum), 4 accumulates.
// Softmax without max-shift (|d| <~ 3; exp cannot overflow fp32).
// ---------------------------------------------------------------------------
__global__ void __launch_bounds__(128) p1_kernel(int pass) {
    __shared__ float wsum[2][4][4];   // [buf][warp][t]

    const int cta = blockIdx.x;
    const int tid = threadIdx.x;
    const int warp = tid >> 5;
    const int lane = tid & 31;
    const int b = cta >> 6;               // 32 b's
    const int i0 = (cta & 63) * 32;       // 64 chunks of 32 i's
    const int o = warp * 16 + (lane >> 1);
    const int vh = lane & 1;              // v in [vh*16, vh*16+16)
    float* Sout = (pass == 1) ? g_S1 : g_S2;

    // Vacc half-row for this (o, vh): 16 floats
    float va[16];
    {
        const float4* vp = (const float4*)(g_Vacc + (size_t)(b * O + o) * VO + vh * 16);
#pragma unroll
        for (int j = 0; j < 4; j++) {
            float4 t4 = vp[j];
            va[4 * j + 0] = t4.x; va[4 * j + 1] = t4.y;
            va[4 * j + 2] = t4.z; va[4 * j + 3] = t4.w;
        }
    }

    float sa[16];
#pragma unroll
    for (int v = 0; v < 16; v++) sa[v] = 0.f;

    // half-row base (in uint4): ((b*I+i)*O + o)*4 + vh*2
    const uint4* up = (const uint4*)g_uhat;
    const size_t rbase = (((size_t)b * I + i0) * O + o) * 4 + (size_t)vh * 2;
    const size_t rstride = (size_t)O * 4;   // per-i

    for (int ib = 0; ib < 8; ib++) {
        // ---- load batch: 4 i's, 8 independent 16B loads ----
        uint4 c0[4], c1[4];
#pragma unroll
        for (int t = 0; t < 4; t++) {
            size_t rb = rbase + (size_t)(ib * 4 + t) * rstride;
            c0[t] = __ldcs(up + rb + 0);
            c1[t] = __ldcs(up + rb + 1);
        }

        // ---- 4 independent half-dots ----
        float d[4];
#pragma unroll
        for (int t = 0; t < 4; t++) {
            unsigned int r[8] = {c0[t].x, c0[t].y, c0[t].z, c0[t].w,
                                 c1[t].x, c1[t].y, c1[t].z, c1[t].w};
            float dd = 0.f;
#pragma unroll
            for (int j = 0; j < 8; j++) {
                float2 f = __half22float2(*(const __half2*)&r[j]);
                dd = fmaf(f.x, va[2 * j + 0], dd);
                dd = fmaf(f.y, va[2 * j + 1], dd);
            }
            d[t] = dd;
        }
        // complete dots with partner lane (4 independent shfls)
#pragma unroll
        for (int t = 0; t < 4; t++)
            d[t] += __shfl_xor_sync(0xffffffffu, d[t], 1);

        // ---- exp + interleaved warp reduces ----
        float e[4], es[4];
#pragma unroll
        for (int t = 0; t < 4; t++) { e[t] = __expf(d[t]); es[t] = e[t]; }
#pragma unroll
        for (int off = 16; off; off >>= 1) {
#pragma unroll
            for (int t = 0; t < 4; t++)
                es[t] += __shfl_xor_sync(0xffffffffu, es[t], off);
        }
        if (lane == 0) {
#pragma unroll
            for (int t = 0; t < 4; t++)
                wsum[ib & 1][warp][t] = es[t];   // = 2 * sum over warp's 16 o's
        }
        __syncthreads();

        // ---- coefficients + accumulate (4 i's) ----
#pragma unroll
        for (int t = 0; t < 4; t++) {
            float tot = (wsum[ib & 1][0][t] + wsum[ib & 1][1][t] +
                         wsum[ib & 1][2][t] + wsum[ib & 1][3][t]) * 0.5f;
            float c = e[t] * __frcp_rn(tot);
            unsigned int r[8] = {c0[t].x, c0[t].y, c0[t].z, c0[t].w,
                                 c1[t].x, c1[t].y, c1[t].z, c1[t].w};
#pragma unroll
            for (int j = 0; j < 8; j++) {
                float2 f = __half22float2(*(const __half2*)&r[j]);
                sa[2 * j + 0] = fmaf(c, f.x, sa[2 * j + 0]);
                sa[2 * j + 1] = fmaf(c, f.y, sa[2 * j + 1]);
            }
        }
        // (no second barrier: buffer ib&1 is rewritten at ib+2, after the
        //  ib+1 barrier, by which time these reads are done)
    }

    float* sp = Sout + (size_t)(b * O + o) * VO + vh * 16;
#pragma unroll
    for (int v = 0; v < 16; v++)
        atomicAdd(&sp[v], sa[v]);
}

// ---------------------------------------------------------------------------
// Squash. which==0: reduce g_S0part over 256 i-blocks, v0=squash(S0/64),
//                   Vacc=v0.
//         which==1: v1=squash(S1), Vacc+=v1.
//         which==2: out=squash(S2).
// ---------------------------------------------------------------------------
__global__ void kv_kernel(int which, float* __restrict__ out) {
    int wid = threadIdx.x >> 5;
    int lane = threadIdx.x & 31;
    int pair = blockIdx.x * (blockDim.x >> 5) + wid;
    if (pair >= B * O) return;
    int idx = pair * VO + lane;

    float s;
    if (which == 0) {
        const float* pp = g_S0part + (size_t)pair * VO + lane;
        const size_t stride = (size_t)B * O * VO;
        float acc = 0.f;
#pragma unroll 8
        for (int k = 0; k < NIBLK; k++)
            acc += __ldcs(pp + (size_t)k * stride);
        s = acc * (1.0f / (float)O);
    } else if (which == 1) {
        s = g_S1[idx];
    } else {
        s = g_S2[idx];
    }

    float sq = s * s;
#pragma unroll
    for (int off = 16; off; off >>= 1)
        sq += __shfl_xor_sync(0xffffffffu, sq, off);

    float scale = (sq / (1.0f + sq)) * rsqrtf(sq + 1e-8f);
    float v = s * scale;

    if (which == 0)      g_Vacc[idx] = v;
    else if (which == 1) g_Vacc[idx] += v;
    else                 out[idx] = v;
}

// ---------------------------------------------------------------------------
extern "C" void kernel_launch(void* const* d_in, const int* in_sizes, int n_in,
                              void* d_out, int out_size) {
    const float* x;
    const float* W;
    if (in_sizes[0] == B * I * VI) {
        x = (const float*)d_in[0];
        W = (const float*)d_in[1];
    } else {
        x = (const float*)d_in[1];
        W = (const float*)d_in[0];
    }
    float* out = (float*)d_out;

    zero_kernel<<<(B * O * VO + 255) / 256, 256>>>();

    // P0: u_hat (fp16) via mma.sync + fused S0 partials
    p0_mma<<<dim3(NIBLK, O / 8), 256>>>(W, x);

    // Iteration 0: reduce S0 partials + squash
    kv_kernel<<<64, 1024>>>(0, out);   // v0 = squash(S0/64); Vacc = v0

    // Iteration 1: logits = u_hat . v0   (raw launch idx 5 -> ncu target)
    p1_kernel<<<2048, 128>>>(1);
    kv_kernel<<<64, 1024>>>(1, out);   // v1 = squash(S1); Vacc = v0 + v1

    // Iteration 2: logits = u_hat . (v0 + v1)
    p1_kernel<<<2048, 128>>>(2);
    kv_kernel<<<64, 1024>>>(2, out);   // out = squash(S2)
}